// round 1
// baseline (speedup 1.0000x reference)
#include <cuda_runtime.h>
#include <cuda_bf16.h>
#include <math_constants.h>

// Problem constants (fixed by the dataset)
#define NN   50000
#define EE   800000
#define INF_ 256
#define OUTF 64
#define NHEAD 4
#define FEAT (NHEAD*OUTF)   // 256
#define ALPHA 0.2f

// -------- device scratch (static; allocation-free) --------
__device__ float g_h[(size_t)NN * FEAT];     // projected features
__device__ float g_hl[NN * NHEAD];
__device__ float g_hr[NN * NHEAD];
__device__ float g_escr[(size_t)EE * NHEAD]; // per-edge scores (CSR order)
__device__ int   g_deg[NN];
__device__ int   g_rowptr[NN + 1];
__device__ int   g_cursor[NN];
__device__ int   g_cols[EE];

// ================= GEMM: H = X @ W  (fp32, 128x64x16 tiles) =================
#define BM 128
#define BN 64
#define BK 16

__global__ __launch_bounds__(256) void gemm_kernel(const float* __restrict__ X,
                                                   const float* __restrict__ W) {
    __shared__ float As[BK][BM];
    __shared__ float Bs[BK][BN];
    int tid = threadIdx.x;
    int bm = blockIdx.y * BM;
    int bn = blockIdx.x * BN;
    int tx = tid & 15;   // 0..15  (cols of 4)
    int ty = tid >> 4;   // 0..15  (rows of 8)

    float acc[8][4];
#pragma unroll
    for (int i = 0; i < 8; i++)
#pragma unroll
        for (int j = 0; j < 4; j++) acc[i][j] = 0.f;

    for (int k0 = 0; k0 < INF_; k0 += BK) {
        // load A tile: 128 rows x 16 k  (512 float4, 2 per thread)
#pragma unroll
        for (int t = 0; t < 2; t++) {
            int f = tid * 2 + t;          // 0..511
            int m = f >> 2;
            int kq = (f & 3) * 4;
            int row = bm + m;
            float4 v = make_float4(0.f, 0.f, 0.f, 0.f);
            if (row < NN) v = *(const float4*)(X + (size_t)row * INF_ + k0 + kq);
            As[kq + 0][m] = v.x;
            As[kq + 1][m] = v.y;
            As[kq + 2][m] = v.z;
            As[kq + 3][m] = v.w;
        }
        // load B tile: 16 rows x 64 cols (256 float4, 1 per thread)
        {
            int kr = tid >> 4;
            int nq = (tid & 15) * 4;
            float4 v = *(const float4*)(W + (size_t)(k0 + kr) * FEAT + bn + nq);
            *(float4*)&Bs[kr][nq] = v;
        }
        __syncthreads();
#pragma unroll
        for (int k = 0; k < BK; k++) {
            float4 b4 = *(float4*)&Bs[k][tx * 4];
            float b[4] = {b4.x, b4.y, b4.z, b4.w};
            float a[8];
#pragma unroll
            for (int i = 0; i < 8; i++) a[i] = As[k][ty * 8 + i];
#pragma unroll
            for (int i = 0; i < 8; i++)
#pragma unroll
                for (int j = 0; j < 4; j++) acc[i][j] = fmaf(a[i], b[j], acc[i][j]);
        }
        __syncthreads();
    }
#pragma unroll
    for (int i = 0; i < 8; i++) {
        int row = bm + ty * 8 + i;
        if (row < NN) {
            float4 v = make_float4(acc[i][0], acc[i][1], acc[i][2], acc[i][3]);
            *(float4*)(g_h + (size_t)row * FEAT + bn + tx * 4) = v;
        }
    }
}

// ============== per-node attention logits: hl = sum(a_l*h), hr = sum(a_r*h) ==============
__global__ __launch_bounds__(256) void logits_kernel(const float* __restrict__ al,
                                                     const float* __restrict__ ar) {
    int warp = (blockIdx.x * blockDim.x + threadIdx.x) >> 5;
    int lane = threadIdx.x & 31;
    if (warp >= NN) return;
    const float* hrow = g_h + (size_t)warp * FEAT;
    float sl[NHEAD] = {0.f, 0.f, 0.f, 0.f};
    float sr[NHEAD] = {0.f, 0.f, 0.f, 0.f};
#pragma unroll
    for (int k = 0; k < 8; k++) {
        int idx = k * 32 + lane;
        float v = hrow[idx];
        sl[k >> 1] = fmaf(v, al[idx], sl[k >> 1]);
        sr[k >> 1] = fmaf(v, ar[idx], sr[k >> 1]);
    }
#pragma unroll
    for (int h = 0; h < NHEAD; h++) {
        float a = sl[h], b = sr[h];
#pragma unroll
        for (int o = 16; o; o >>= 1) {
            a += __shfl_xor_sync(0xffffffffu, a, o);
            b += __shfl_xor_sync(0xffffffffu, b, o);
        }
        if (lane == 0) {
            g_hl[warp * NHEAD + h] = a;
            g_hr[warp * NHEAD + h] = b;
        }
    }
}

// ============== CSR build ==============
__global__ void zero_deg_kernel() {
    int i = blockIdx.x * blockDim.x + threadIdx.x;
    if (i < NN) g_deg[i] = 0;
}

__global__ void hist_kernel(const int* __restrict__ edge) {
    int e = blockIdx.x * blockDim.x + threadIdx.x;
    if (e < EE) atomicAdd(&g_deg[edge[e]], 1);   // edge[0][e] = row
}

__global__ __launch_bounds__(1024) void scan_kernel() {
    __shared__ int warp_sums[32];
    __shared__ int s_carry;
    int tid = threadIdx.x;
    int lane = tid & 31, w = tid >> 5;
    if (tid == 0) { s_carry = 0; g_rowptr[0] = 0; }
    __syncthreads();
    for (int base = 0; base < NN; base += 1024) {
        int i = base + tid;
        int v = (i < NN) ? g_deg[i] : 0;
        int x = v;
#pragma unroll
        for (int o = 1; o < 32; o <<= 1) {
            int y = __shfl_up_sync(0xffffffffu, x, o);
            if (lane >= o) x += y;
        }
        if (lane == 31) warp_sums[w] = x;
        __syncthreads();
        if (w == 0) {
            int s = warp_sums[lane];
#pragma unroll
            for (int o = 1; o < 32; o <<= 1) {
                int y = __shfl_up_sync(0xffffffffu, s, o);
                if (lane >= o) s += y;
            }
            warp_sums[lane] = s;
        }
        __syncthreads();
        int incl = x + (w > 0 ? warp_sums[w - 1] : 0) + s_carry;
        if (i < NN) {
            g_rowptr[i + 1] = incl;
            g_cursor[i] = incl - v;   // exclusive prefix
        }
        __syncthreads();
        if (tid == 1023) s_carry = incl;
        __syncthreads();
    }
}

__global__ void scatter_kernel(const int* __restrict__ edge) {
    int e = blockIdx.x * blockDim.x + threadIdx.x;
    if (e < EE) {
        int r = edge[e];
        int c = edge[EE + e];
        int pos = atomicAdd(&g_cursor[r], 1);
        g_cols[pos] = c;
    }
}

// ============== fused softmax + SpMM: one warp per destination row ==============
__global__ __launch_bounds__(256) void aggregate_kernel(float* __restrict__ out) {
    int warp = (blockIdx.x * blockDim.x + threadIdx.x) >> 5;
    int lane = threadIdx.x & 31;
    if (warp >= NN) return;
    int start = g_rowptr[warp];
    int end = g_rowptr[warp + 1];
    float* orow = out + (size_t)warp * FEAT + lane * 8;
    if (start == end) {
        float4 z = make_float4(0.f, 0.f, 0.f, 0.f);
        *(float4*)orow = z;
        *(float4*)(orow + 4) = z;
        return;
    }
    float4 hl4 = *(const float4*)(g_hl + warp * NHEAD);
    float mx0 = -CUDART_INF_F, mx1 = -CUDART_INF_F, mx2 = -CUDART_INF_F, mx3 = -CUDART_INF_F;

    // pass 1: per-edge scores, track per-head max
    for (int j = start + lane; j < end; j += 32) {
        int c = g_cols[j];
        float4 hr4 = *(const float4*)(g_hr + c * NHEAD);
        float e0 = hl4.x + hr4.x; e0 = e0 > 0.f ? e0 : ALPHA * e0;
        float e1 = hl4.y + hr4.y; e1 = e1 > 0.f ? e1 : ALPHA * e1;
        float e2 = hl4.z + hr4.z; e2 = e2 > 0.f ? e2 : ALPHA * e2;
        float e3 = hl4.w + hr4.w; e3 = e3 > 0.f ? e3 : ALPHA * e3;
        mx0 = fmaxf(mx0, e0); mx1 = fmaxf(mx1, e1);
        mx2 = fmaxf(mx2, e2); mx3 = fmaxf(mx3, e3);
        *(float4*)(g_escr + (size_t)j * NHEAD) = make_float4(e0, e1, e2, e3);
    }
#pragma unroll
    for (int o = 16; o; o >>= 1) {
        mx0 = fmaxf(mx0, __shfl_xor_sync(0xffffffffu, mx0, o));
        mx1 = fmaxf(mx1, __shfl_xor_sync(0xffffffffu, mx1, o));
        mx2 = fmaxf(mx2, __shfl_xor_sync(0xffffffffu, mx2, o));
        mx3 = fmaxf(mx3, __shfl_xor_sync(0xffffffffu, mx3, o));
    }
    int head = lane >> 3;   // lane handles features [lane*8, lane*8+8) -> head = lane/8
    float mxh = (head == 0) ? mx0 : (head == 1) ? mx1 : (head == 2) ? mx2 : mx3;

    // pass 2: exp, denom, and gather-accumulate h[col]
    float den = 0.f;
    float4 acc0 = make_float4(0.f, 0.f, 0.f, 0.f);
    float4 acc1 = make_float4(0.f, 0.f, 0.f, 0.f);
    for (int j = start; j < end; j++) {
        int c = g_cols[j];                                    // broadcast
        float4 e4 = *(const float4*)(g_escr + (size_t)j * NHEAD);  // broadcast
        float eh = (head == 0) ? e4.x : (head == 1) ? e4.y : (head == 2) ? e4.z : e4.w;
        float ee = __expf(eh - mxh);
        den += ee;
        const float* hc = g_h + (size_t)c * FEAT + lane * 8;
        float4 a = *(const float4*)hc;
        float4 b = *(const float4*)(hc + 4);
        acc0.x = fmaf(ee, a.x, acc0.x);
        acc0.y = fmaf(ee, a.y, acc0.y);
        acc0.z = fmaf(ee, a.z, acc0.z);
        acc0.w = fmaf(ee, a.w, acc0.w);
        acc1.x = fmaf(ee, b.x, acc1.x);
        acc1.y = fmaf(ee, b.y, acc1.y);
        acc1.z = fmaf(ee, b.z, acc1.z);
        acc1.w = fmaf(ee, b.w, acc1.w);
    }
    float inv = 1.0f / den;
    acc0.x *= inv; acc0.y *= inv; acc0.z *= inv; acc0.w *= inv;
    acc1.x *= inv; acc1.y *= inv; acc1.z *= inv; acc1.w *= inv;
    *(float4*)orow = acc0;
    *(float4*)(orow + 4) = acc1;
}

// ================= launch =================
extern "C" void kernel_launch(void* const* d_in, const int* in_sizes, int n_in,
                              void* d_out, int out_size) {
    const float* x  = (const float*)d_in[0];
    const int*   eg = (const int*)d_in[1];
    const float* W  = (const float*)d_in[2];
    const float* al = (const float*)d_in[3];
    const float* ar = (const float*)d_in[4];
    float* out = (float*)d_out;

    dim3 ggrid(FEAT / BN, (NN + BM - 1) / BM);
    gemm_kernel<<<ggrid, 256>>>(x, W);

    logits_kernel<<<(NN * 32 + 255) / 256, 256>>>(al, ar);

    zero_deg_kernel<<<(NN + 255) / 256, 256>>>();
    hist_kernel<<<(EE + 255) / 256, 256>>>(eg);
    scan_kernel<<<1, 1024>>>();
    scatter_kernel<<<(EE + 255) / 256, 256>>>(eg);

    aggregate_kernel<<<(NN * 32 + 255) / 256, 256>>>(out);
}

// round 2
// speedup vs baseline: 1.0963x; 1.0963x over previous
#include <cuda_runtime.h>
#include <cuda_bf16.h>
#include <math_constants.h>

// Problem constants (fixed by the dataset)
#define NN   50000
#define EE   800000
#define INF_ 256
#define OUTF 64
#define NHEAD 4
#define FEAT (NHEAD*OUTF)   // 256
#define ALPHA 0.2f

// -------- device scratch (static; allocation-free) --------
__device__ float g_h[(size_t)NN * FEAT];     // projected features
__device__ float g_hl[NN * NHEAD];
__device__ float g_hr[NN * NHEAD];
__device__ float g_escr[(size_t)EE * NHEAD]; // per-edge scores (CSR order)
__device__ int   g_deg[NN];
__device__ int   g_rowptr[NN + 1];
__device__ int   g_cursor[NN];
__device__ int   g_cols[EE];

// ====================== tf32 tensor-core GEMM: H = X @ W ======================
// Block tile 128x64, BK=32. 256 threads = 8 warps as 4(M) x 2(N), warp tile 32x32.
// Each warp: 2 (m16) x 4 (n8) mma.sync.m16n8k8 tf32 tiles.
#define GBM 128
#define GBN 64
#define GBK 32
#define AS_STRIDE 36   // bank = (4r + k) % 32 -> conflict-free fragment loads
#define BS_STRIDE 68   // bank = (4k + n) % 32 -> conflict-free fragment loads

__device__ __forceinline__ float f2tf32(float x) {
    unsigned r;
    asm("cvt.rna.tf32.f32 %0, %1;" : "=r"(r) : "f"(x));
    return __uint_as_float(r);
}

__device__ __forceinline__ void mma_tf32(float c[4], unsigned a0, unsigned a1,
                                         unsigned a2, unsigned a3,
                                         unsigned b0, unsigned b1) {
    asm volatile(
        "mma.sync.aligned.m16n8k8.row.col.f32.tf32.tf32.f32 "
        "{%0,%1,%2,%3}, {%4,%5,%6,%7}, {%8,%9}, {%0,%1,%2,%3};"
        : "+f"(c[0]), "+f"(c[1]), "+f"(c[2]), "+f"(c[3])
        : "r"(a0), "r"(a1), "r"(a2), "r"(a3), "r"(b0), "r"(b1));
}

__global__ __launch_bounds__(256) void gemm_tf32_kernel(const float* __restrict__ X,
                                                        const float* __restrict__ W) {
    __shared__ float As[GBM][AS_STRIDE];   // [row][k]
    __shared__ float Bs[GBK][BS_STRIDE];   // [k][n]
    int tid = threadIdx.x;
    int lane = tid & 31;
    int wid = tid >> 5;
    int wm = wid >> 1;      // 0..3
    int wn = wid & 1;       // 0..1
    int bm = blockIdx.y * GBM;
    int bn = blockIdx.x * GBN;

    float acc[2][4][4];
#pragma unroll
    for (int mt = 0; mt < 2; mt++)
#pragma unroll
        for (int nt = 0; nt < 4; nt++)
#pragma unroll
            for (int q = 0; q < 4; q++) acc[mt][nt][q] = 0.f;

    int g = lane >> 2;      // groupID 0..7
    int tg = lane & 3;      // thread-in-group 0..3

    for (int k0 = 0; k0 < INF_; k0 += GBK) {
        // A tile: 128 rows x 32 k = 1024 float4, 4 per thread
#pragma unroll
        for (int i = 0; i < 4; i++) {
            int f = tid + i * 256;
            int r = f >> 3;
            int c4 = (f & 7) * 4;
            int row = bm + r;
            float4 v = make_float4(0.f, 0.f, 0.f, 0.f);
            if (row < NN) v = *(const float4*)(X + (size_t)row * INF_ + k0 + c4);
            As[r][c4 + 0] = f2tf32(v.x);
            As[r][c4 + 1] = f2tf32(v.y);
            As[r][c4 + 2] = f2tf32(v.z);
            As[r][c4 + 3] = f2tf32(v.w);
        }
        // B tile: 32 k x 64 n = 512 float4, 2 per thread
#pragma unroll
        for (int i = 0; i < 2; i++) {
            int f = tid + i * 256;
            int kr = f >> 4;
            int c4 = (f & 15) * 4;
            float4 v = *(const float4*)(W + (size_t)(k0 + kr) * FEAT + bn + c4);
            Bs[kr][c4 + 0] = f2tf32(v.x);
            Bs[kr][c4 + 1] = f2tf32(v.y);
            Bs[kr][c4 + 2] = f2tf32(v.z);
            Bs[kr][c4 + 3] = f2tf32(v.w);
        }
        __syncthreads();

#pragma unroll
        for (int kk = 0; kk < GBK / 8; kk++) {
            int kb = kk * 8;
            unsigned a[2][4];
#pragma unroll
            for (int mt = 0; mt < 2; mt++) {
                int r0 = wm * 32 + mt * 16 + g;
                a[mt][0] = __float_as_uint(As[r0][kb + tg]);
                a[mt][1] = __float_as_uint(As[r0 + 8][kb + tg]);
                a[mt][2] = __float_as_uint(As[r0][kb + tg + 4]);
                a[mt][3] = __float_as_uint(As[r0 + 8][kb + tg + 4]);
            }
            unsigned b[4][2];
#pragma unroll
            for (int nt = 0; nt < 4; nt++) {
                int n = wn * 32 + nt * 8 + g;
                b[nt][0] = __float_as_uint(Bs[kb + tg][n]);
                b[nt][1] = __float_as_uint(Bs[kb + tg + 4][n]);
            }
#pragma unroll
            for (int mt = 0; mt < 2; mt++)
#pragma unroll
                for (int nt = 0; nt < 4; nt++)
                    mma_tf32(acc[mt][nt], a[mt][0], a[mt][1], a[mt][2], a[mt][3],
                             b[nt][0], b[nt][1]);
        }
        __syncthreads();
    }

    // epilogue: c0,c1 at (row=g, col=2*tg..+1); c2,c3 at row=g+8
#pragma unroll
    for (int mt = 0; mt < 2; mt++) {
#pragma unroll
        for (int nt = 0; nt < 4; nt++) {
            int row0 = bm + wm * 32 + mt * 16 + g;
            int col = bn + wn * 32 + nt * 8 + tg * 2;
            if (row0 < NN)
                *(float2*)(g_h + (size_t)row0 * FEAT + col) =
                    make_float2(acc[mt][nt][0], acc[mt][nt][1]);
            int row1 = row0 + 8;
            if (row1 < NN)
                *(float2*)(g_h + (size_t)row1 * FEAT + col) =
                    make_float2(acc[mt][nt][2], acc[mt][nt][3]);
        }
    }
}

// ============== per-node attention logits: hl = sum(a_l*h), hr = sum(a_r*h) ==============
__global__ __launch_bounds__(256) void logits_kernel(const float* __restrict__ al,
                                                     const float* __restrict__ ar) {
    int warp = (blockIdx.x * blockDim.x + threadIdx.x) >> 5;
    int lane = threadIdx.x & 31;
    if (warp >= NN) return;
    const float* hrow = g_h + (size_t)warp * FEAT;
    float sl[NHEAD] = {0.f, 0.f, 0.f, 0.f};
    float sr[NHEAD] = {0.f, 0.f, 0.f, 0.f};
#pragma unroll
    for (int k = 0; k < 8; k++) {
        int idx = k * 32 + lane;
        float v = hrow[idx];
        sl[k >> 1] = fmaf(v, al[idx], sl[k >> 1]);
        sr[k >> 1] = fmaf(v, ar[idx], sr[k >> 1]);
    }
#pragma unroll
    for (int h = 0; h < NHEAD; h++) {
        float a = sl[h], b = sr[h];
#pragma unroll
        for (int o = 16; o; o >>= 1) {
            a += __shfl_xor_sync(0xffffffffu, a, o);
            b += __shfl_xor_sync(0xffffffffu, b, o);
        }
        if (lane == 0) {
            g_hl[warp * NHEAD + h] = a;
            g_hr[warp * NHEAD + h] = b;
        }
    }
}

// ============== CSR build ==============
__global__ void zero_deg_kernel() {
    int i = blockIdx.x * blockDim.x + threadIdx.x;
    if (i < NN) g_deg[i] = 0;
}

__global__ void hist_kernel(const int* __restrict__ edge) {
    int e = blockIdx.x * blockDim.x + threadIdx.x;
    if (e < EE) atomicAdd(&g_deg[edge[e]], 1);   // edge[0][e] = row
}

// single-block scan, 8 elements per thread (7 iterations over 50000)
__global__ __launch_bounds__(1024) void scan_kernel() {
    __shared__ int warp_sums[32];
    __shared__ int s_carry;
    int tid = threadIdx.x;
    int lane = tid & 31, w = tid >> 5;
    if (tid == 0) { s_carry = 0; g_rowptr[0] = 0; }
    __syncthreads();
    for (int base = 0; base < NN; base += 8192) {
        int i0 = base + tid * 8;
        int v[8];
#pragma unroll
        for (int j = 0; j < 8; j++) {
            int i = i0 + j;
            v[j] = (i < NN) ? g_deg[i] : 0;
        }
#pragma unroll
        for (int j = 1; j < 8; j++) v[j] += v[j - 1];   // inclusive within thread
        int x = v[7];
#pragma unroll
        for (int o = 1; o < 32; o <<= 1) {
            int y = __shfl_up_sync(0xffffffffu, x, o);
            if (lane >= o) x += y;
        }
        if (lane == 31) warp_sums[w] = x;
        __syncthreads();
        if (w == 0) {
            int s = warp_sums[lane];
#pragma unroll
            for (int o = 1; o < 32; o <<= 1) {
                int y = __shfl_up_sync(0xffffffffu, s, o);
                if (lane >= o) s += y;
            }
            warp_sums[lane] = s;
        }
        __syncthreads();
        int off = (x - v[7]) + (w > 0 ? warp_sums[w - 1] : 0) + s_carry;
#pragma unroll
        for (int j = 0; j < 8; j++) {
            int i = i0 + j;
            if (i < NN) {
                int incl = off + v[j];
                g_rowptr[i + 1] = incl;
                g_cursor[i] = off + (j > 0 ? v[j - 1] : 0);   // exclusive
            }
        }
        __syncthreads();
        if (tid == 0) s_carry += warp_sums[31];
        __syncthreads();
    }
}

__global__ void scatter_kernel(const int* __restrict__ edge) {
    int e = blockIdx.x * blockDim.x + threadIdx.x;
    if (e < EE) {
        int r = edge[e];
        int c = edge[EE + e];
        int pos = atomicAdd(&g_cursor[r], 1);
        g_cols[pos] = c;
    }
}

// ============== fused softmax + SpMM: one warp per destination row ==============
__global__ __launch_bounds__(256) void aggregate_kernel(float* __restrict__ out) {
    int warp = (blockIdx.x * blockDim.x + threadIdx.x) >> 5;
    int lane = threadIdx.x & 31;
    if (warp >= NN) return;
    int start = g_rowptr[warp];
    int end = g_rowptr[warp + 1];
    float* orow = out + (size_t)warp * FEAT + lane * 8;
    if (start == end) {
        float4 z = make_float4(0.f, 0.f, 0.f, 0.f);
        *(float4*)orow = z;
        *(float4*)(orow + 4) = z;
        return;
    }
    float4 hl4 = *(const float4*)(g_hl + warp * NHEAD);
    float mx0 = -CUDART_INF_F, mx1 = -CUDART_INF_F, mx2 = -CUDART_INF_F, mx3 = -CUDART_INF_F;

    // pass 1: per-edge scores, track per-head max
    for (int j = start + lane; j < end; j += 32) {
        int c = g_cols[j];
        float4 hr4 = *(const float4*)(g_hr + c * NHEAD);
        float e0 = hl4.x + hr4.x; e0 = e0 > 0.f ? e0 : ALPHA * e0;
        float e1 = hl4.y + hr4.y; e1 = e1 > 0.f ? e1 : ALPHA * e1;
        float e2 = hl4.z + hr4.z; e2 = e2 > 0.f ? e2 : ALPHA * e2;
        float e3 = hl4.w + hr4.w; e3 = e3 > 0.f ? e3 : ALPHA * e3;
        mx0 = fmaxf(mx0, e0); mx1 = fmaxf(mx1, e1);
        mx2 = fmaxf(mx2, e2); mx3 = fmaxf(mx3, e3);
        *(float4*)(g_escr + (size_t)j * NHEAD) = make_float4(e0, e1, e2, e3);
    }
#pragma unroll
    for (int o = 16; o; o >>= 1) {
        mx0 = fmaxf(mx0, __shfl_xor_sync(0xffffffffu, mx0, o));
        mx1 = fmaxf(mx1, __shfl_xor_sync(0xffffffffu, mx1, o));
        mx2 = fmaxf(mx2, __shfl_xor_sync(0xffffffffu, mx2, o));
        mx3 = fmaxf(mx3, __shfl_xor_sync(0xffffffffu, mx3, o));
    }
    int head = lane >> 3;
    float mxh = (head == 0) ? mx0 : (head == 1) ? mx1 : (head == 2) ? mx2 : mx3;

    // pass 2: exp, denom, gather-accumulate with depth-1 software pipeline
    float den = 0.f;
    float4 acc0 = make_float4(0.f, 0.f, 0.f, 0.f);
    float4 acc1 = make_float4(0.f, 0.f, 0.f, 0.f);
    {
        int c = g_cols[start];
        float4 e4 = *(const float4*)(g_escr + (size_t)start * NHEAD);
        const float* hc = g_h + (size_t)c * FEAT + lane * 8;
        float4 a = *(const float4*)hc;
        float4 b = *(const float4*)(hc + 4);
        for (int j = start; j < end; j++) {
            float4 ca = a, cb = b, ce = e4;
            int jn = j + 1;
            if (jn < end) {
                int cn = g_cols[jn];
                e4 = *(const float4*)(g_escr + (size_t)jn * NHEAD);
                const float* hn = g_h + (size_t)cn * FEAT + lane * 8;
                a = *(const float4*)hn;
                b = *(const float4*)(hn + 4);
            }
            float eh = (head == 0) ? ce.x : (head == 1) ? ce.y : (head == 2) ? ce.z : ce.w;
            float ee = __expf(eh - mxh);
            den += ee;
            acc0.x = fmaf(ee, ca.x, acc0.x);
            acc0.y = fmaf(ee, ca.y, acc0.y);
            acc0.z = fmaf(ee, ca.z, acc0.z);
            acc0.w = fmaf(ee, ca.w, acc0.w);
            acc1.x = fmaf(ee, cb.x, acc1.x);
            acc1.y = fmaf(ee, cb.y, acc1.y);
            acc1.z = fmaf(ee, cb.z, acc1.z);
            acc1.w = fmaf(ee, cb.w, acc1.w);
        }
    }
    float inv = 1.0f / den;
    acc0.x *= inv; acc0.y *= inv; acc0.z *= inv; acc0.w *= inv;
    acc1.x *= inv; acc1.y *= inv; acc1.z *= inv; acc1.w *= inv;
    *(float4*)orow = acc0;
    *(float4*)(orow + 4) = acc1;
}

// ================= launch =================
extern "C" void kernel_launch(void* const* d_in, const int* in_sizes, int n_in,
                              void* d_out, int out_size) {
    const float* x  = (const float*)d_in[0];
    const int*   eg = (const int*)d_in[1];
    const float* W  = (const float*)d_in[2];
    const float* al = (const float*)d_in[3];
    const float* ar = (const float*)d_in[4];
    float* out = (float*)d_out;

    dim3 ggrid(FEAT / GBN, (NN + GBM - 1) / GBM);
    gemm_tf32_kernel<<<ggrid, 256>>>(x, W);

    logits_kernel<<<(NN * 32 + 255) / 256, 256>>>(al, ar);

    zero_deg_kernel<<<(NN + 255) / 256, 256>>>();
    hist_kernel<<<(EE + 255) / 256, 256>>>(eg);
    scan_kernel<<<1, 1024>>>();
    scatter_kernel<<<(EE + 255) / 256, 256>>>(eg);

    aggregate_kernel<<<(NN * 32 + 255) / 256, 256>>>(out);
}

// round 3
// speedup vs baseline: 1.1415x; 1.0412x over previous
#include <cuda_runtime.h>
#include <cuda_bf16.h>
#include <math_constants.h>

#define NN   50000
#define EE   800000
#define INF_ 256
#define OUTF 64
#define NHEAD 4
#define FEAT (NHEAD*OUTF)   // 256
#define ALPHA 0.2f

// -------- device scratch (static; allocation-free) --------
__device__ float g_h[(size_t)NN * FEAT];
__device__ float g_hl[NN * NHEAD];
__device__ float g_hr[NN * NHEAD];
__device__ float g_escr[(size_t)EE * NHEAD];
__device__ int   g_deg[NN];
__device__ int   g_rowptr[NN + 1];
__device__ int   g_cursor[NN];
__device__ int   g_cols[EE];

// ====================== tf32 tensor-core GEMM: H = X @ W ======================
// Block 128x64, BK=32, 128 threads = 4 warps (2M x 2N), warp tile 64x32.
// Fragment-major smem:
//  A: elem(r,k) -> kk=k>>3 (stride 1064, ==8 mod 32, 16B-aligned), rgrp=r>>4 (stride 128),
//     g=r&7 (stride 16), tg=k&3 (stride 4), slot=((r>>3)&1) + 2*((k>>2)&1)
//     -> inner-loop A fragment = one LDS.128, conflict-free.
//  B: elem(k,n) -> kk=k>>3 (stride 520, ==8 mod 32), n (stride 8), p=2*(k&3)+((k>>2)&1)
//     -> inner-loop B fragment = one LDS.64, conflict-free; STS conflict-free.
#define A_STAGE 4256   // 4*1064 floats
#define B_STAGE 2080   // 4*520 floats
#define GEMM_SMEM_BYTES ((2*A_STAGE + 2*B_STAGE)*4)

__device__ __forceinline__ float f2tf32(float x) {
    unsigned r;
    asm("cvt.rna.tf32.f32 %0, %1;" : "=r"(r) : "f"(x));
    return __uint_as_float(r);
}

__device__ __forceinline__ void mma_tf32(float c[4], float a0, float a1, float a2,
                                         float a3, float b0, float b1) {
    asm volatile(
        "mma.sync.aligned.m16n8k8.row.col.f32.tf32.tf32.f32 "
        "{%0,%1,%2,%3}, {%4,%5,%6,%7}, {%8,%9}, {%0,%1,%2,%3};"
        : "+f"(c[0]), "+f"(c[1]), "+f"(c[2]), "+f"(c[3])
        : "r"(__float_as_uint(a0)), "r"(__float_as_uint(a1)),
          "r"(__float_as_uint(a2)), "r"(__float_as_uint(a3)),
          "r"(__float_as_uint(b0)), "r"(__float_as_uint(b1)));
}

__global__ __launch_bounds__(128) void gemm_tf32_kernel(const float* __restrict__ X,
                                                        const float* __restrict__ W) {
    extern __shared__ float smem[];
    float* sA = smem;                  // [2][A_STAGE]
    float* sB = smem + 2 * A_STAGE;    // [2][B_STAGE]
    int tid = threadIdx.x;
    int lane = tid & 31;
    int wid = tid >> 5;
    int wm = wid >> 1, wn = wid & 1;
    int g = lane >> 2, tg = lane & 3;
    int bm = blockIdx.y * 128;
    int bn = blockIdx.x * 64;

    float acc[4][4][4];
#pragma unroll
    for (int mt = 0; mt < 4; mt++)
#pragma unroll
        for (int nt = 0; nt < 4; nt++)
#pragma unroll
            for (int q = 0; q < 4; q++) acc[mt][nt][q] = 0.f;

    float4 ra[8];
    float4 rb[4];

    // ---- prologue: load tile 0 ----
#pragma unroll
    for (int i = 0; i < 8; i++) {
        int f = tid + i * 128;
        int r = f >> 3, c4 = (f & 7) * 4;
        int row = bm + r;
        ra[i] = (row < NN) ? *(const float4*)(X + (size_t)row * INF_ + c4)
                           : make_float4(0.f, 0.f, 0.f, 0.f);
    }
#pragma unroll
    for (int i = 0; i < 4; i++) {
        int f = tid + i * 128;
        int kr = f & 31, nn = (f >> 5) * 4;
        rb[i] = *(const float4*)(W + (size_t)kr * FEAT + bn + nn);
    }
    // STS tile 0 -> stage 0
#pragma unroll
    for (int i = 0; i < 8; i++) {
        int f = tid + i * 128;
        int r = f >> 3, c4 = (f & 7) * 4;
        int kk = c4 >> 3, kbit = (c4 >> 2) & 1;
        float* p = sA + kk * 1064 + (r >> 4) * 128 + (r & 7) * 16 + ((r >> 3) & 1) + 2 * kbit;
        p[0]  = f2tf32(ra[i].x);
        p[4]  = f2tf32(ra[i].y);
        p[8]  = f2tf32(ra[i].z);
        p[12] = f2tf32(ra[i].w);
    }
#pragma unroll
    for (int i = 0; i < 4; i++) {
        int f = tid + i * 128;
        int kr = f & 31, nn = (f >> 5) * 4;
        float* q = sB + (kr >> 3) * 520 + nn * 8 + 2 * (kr & 3) + ((kr >> 2) & 1);
        q[0]  = f2tf32(rb[i].x);
        q[8]  = f2tf32(rb[i].y);
        q[16] = f2tf32(rb[i].z);
        q[24] = f2tf32(rb[i].w);
    }
    __syncthreads();

    for (int kt = 0; kt < 8; kt++) {
        int st = kt & 1;
        // prefetch next tile into regs (latency hidden by compute below)
        if (kt < 7) {
            int k0 = (kt + 1) * 32;
#pragma unroll
            for (int i = 0; i < 8; i++) {
                int f = tid + i * 128;
                int r = f >> 3, c4 = (f & 7) * 4;
                int row = bm + r;
                ra[i] = (row < NN) ? *(const float4*)(X + (size_t)row * INF_ + k0 + c4)
                                   : make_float4(0.f, 0.f, 0.f, 0.f);
            }
#pragma unroll
            for (int i = 0; i < 4; i++) {
                int f = tid + i * 128;
                int kr = f & 31, nn = (f >> 5) * 4;
                rb[i] = *(const float4*)(W + (size_t)(k0 + kr) * FEAT + bn + nn);
            }
        }
        // compute current stage
        {
            const float* As = sA + st * A_STAGE;
            const float* Bs = sB + st * B_STAGE;
#pragma unroll
            for (int kk = 0; kk < 4; kk++) {
                float4 afr[4];
                float2 bfr[4];
#pragma unroll
                for (int mt = 0; mt < 4; mt++)
                    afr[mt] = *(const float4*)(As + kk * 1064 + (wm * 4 + mt) * 128 +
                                               g * 16 + tg * 4);
#pragma unroll
                for (int nt = 0; nt < 4; nt++)
                    bfr[nt] = *(const float2*)(Bs + kk * 520 + (wn * 32 + nt * 8 + g) * 8 +
                                               tg * 2);
#pragma unroll
                for (int mt = 0; mt < 4; mt++)
#pragma unroll
                    for (int nt = 0; nt < 4; nt++)
                        mma_tf32(acc[mt][nt], afr[mt].x, afr[mt].y, afr[mt].z, afr[mt].w,
                                 bfr[nt].x, bfr[nt].y);
            }
        }
        // STS next tile into other stage
        if (kt < 7) {
            float* dA = sA + (1 - st) * A_STAGE;
            float* dB = sB + (1 - st) * B_STAGE;
#pragma unroll
            for (int i = 0; i < 8; i++) {
                int f = tid + i * 128;
                int r = f >> 3, c4 = (f & 7) * 4;
                int kk = c4 >> 3, kbit = (c4 >> 2) & 1;
                float* p = dA + kk * 1064 + (r >> 4) * 128 + (r & 7) * 16 +
                           ((r >> 3) & 1) + 2 * kbit;
                p[0]  = f2tf32(ra[i].x);
                p[4]  = f2tf32(ra[i].y);
                p[8]  = f2tf32(ra[i].z);
                p[12] = f2tf32(ra[i].w);
            }
#pragma unroll
            for (int i = 0; i < 4; i++) {
                int f = tid + i * 128;
                int kr = f & 31, nn = (f >> 5) * 4;
                float* q = dB + (kr >> 3) * 520 + nn * 8 + 2 * (kr & 3) + ((kr >> 2) & 1);
                q[0]  = f2tf32(rb[i].x);
                q[8]  = f2tf32(rb[i].y);
                q[16] = f2tf32(rb[i].z);
                q[24] = f2tf32(rb[i].w);
            }
        }
        __syncthreads();
    }

    // epilogue
#pragma unroll
    for (int mt = 0; mt < 4; mt++) {
#pragma unroll
        for (int nt = 0; nt < 4; nt++) {
            int row0 = bm + wm * 64 + mt * 16 + g;
            int col = bn + wn * 32 + nt * 8 + tg * 2;
            if (row0 < NN)
                *(float2*)(g_h + (size_t)row0 * FEAT + col) =
                    make_float2(acc[mt][nt][0], acc[mt][nt][1]);
            if (row0 + 8 < NN)
                *(float2*)(g_h + (size_t)(row0 + 8) * FEAT + col) =
                    make_float2(acc[mt][nt][2], acc[mt][nt][3]);
        }
    }
}

// ============== per-node attention logits ==============
__global__ __launch_bounds__(256) void logits_kernel(const float* __restrict__ al,
                                                     const float* __restrict__ ar) {
    int warp = (blockIdx.x * blockDim.x + threadIdx.x) >> 5;
    int lane = threadIdx.x & 31;
    if (warp >= NN) return;
    const float* hrow = g_h + (size_t)warp * FEAT;
    float sl[NHEAD] = {0.f, 0.f, 0.f, 0.f};
    float sr[NHEAD] = {0.f, 0.f, 0.f, 0.f};
#pragma unroll
    for (int k = 0; k < 8; k++) {
        int idx = k * 32 + lane;
        float v = hrow[idx];
        sl[k >> 1] = fmaf(v, al[idx], sl[k >> 1]);
        sr[k >> 1] = fmaf(v, ar[idx], sr[k >> 1]);
    }
#pragma unroll
    for (int h = 0; h < NHEAD; h++) {
        float a = sl[h], b = sr[h];
#pragma unroll
        for (int o = 16; o; o >>= 1) {
            a += __shfl_xor_sync(0xffffffffu, a, o);
            b += __shfl_xor_sync(0xffffffffu, b, o);
        }
        if (lane == 0) {
            g_hl[warp * NHEAD + h] = a;
            g_hr[warp * NHEAD + h] = b;
        }
    }
}

// ============== CSR build ==============
__global__ void zero_deg_kernel() {
    int i = blockIdx.x * blockDim.x + threadIdx.x;
    if (i < NN) g_deg[i] = 0;
}

__global__ void hist_kernel(const int* __restrict__ edge) {
    int e = blockIdx.x * blockDim.x + threadIdx.x;
    if (e < EE) atomicAdd(&g_deg[edge[e]], 1);
}

__global__ __launch_bounds__(1024) void scan_kernel() {
    __shared__ int warp_sums[32];
    __shared__ int s_carry;
    int tid = threadIdx.x;
    int lane = tid & 31, w = tid >> 5;
    if (tid == 0) { s_carry = 0; g_rowptr[0] = 0; }
    __syncthreads();
    for (int base = 0; base < NN; base += 8192) {
        int i0 = base + tid * 8;
        int v[8];
#pragma unroll
        for (int j = 0; j < 8; j++) {
            int i = i0 + j;
            v[j] = (i < NN) ? g_deg[i] : 0;
        }
#pragma unroll
        for (int j = 1; j < 8; j++) v[j] += v[j - 1];
        int x = v[7];
#pragma unroll
        for (int o = 1; o < 32; o <<= 1) {
            int y = __shfl_up_sync(0xffffffffu, x, o);
            if (lane >= o) x += y;
        }
        if (lane == 31) warp_sums[w] = x;
        __syncthreads();
        if (w == 0) {
            int s = warp_sums[lane];
#pragma unroll
            for (int o = 1; o < 32; o <<= 1) {
                int y = __shfl_up_sync(0xffffffffu, s, o);
                if (lane >= o) s += y;
            }
            warp_sums[lane] = s;
        }
        __syncthreads();
        int off = (x - v[7]) + (w > 0 ? warp_sums[w - 1] : 0) + s_carry;
#pragma unroll
        for (int j = 0; j < 8; j++) {
            int i = i0 + j;
            if (i < NN) {
                g_rowptr[i + 1] = off + v[j];
                g_cursor[i] = off + (j > 0 ? v[j - 1] : 0);
            }
        }
        __syncthreads();
        if (tid == 0) s_carry += warp_sums[31];
        __syncthreads();
    }
}

__global__ void scatter_kernel(const int* __restrict__ edge) {
    int e = blockIdx.x * blockDim.x + threadIdx.x;
    if (e < EE) {
        int r = edge[e];
        int c = edge[EE + e];
        int pos = atomicAdd(&g_cursor[r], 1);
        g_cols[pos] = c;
    }
}

// ============== fused softmax + SpMM: TWO warps per destination row ==============
// warp = (row, head-pair hp). Warp owns features [hp*128, hp*128+128), lane -> 4 floats.
__global__ __launch_bounds__(256) void aggregate_kernel(float* __restrict__ out) {
    int gw = (blockIdx.x * blockDim.x + threadIdx.x) >> 5;
    int lane = threadIdx.x & 31;
    int row = gw >> 1;
    int hp = gw & 1;
    if (row >= NN) return;
    int start = g_rowptr[row];
    int end = g_rowptr[row + 1];
    float* orow = out + (size_t)row * FEAT + hp * 128 + lane * 4;
    if (start == end) {
        *(float4*)orow = make_float4(0.f, 0.f, 0.f, 0.f);
        return;
    }
    float2 hl2 = *(const float2*)(g_hl + row * NHEAD + hp * 2);
    float mx0 = -CUDART_INF_F, mx1 = -CUDART_INF_F;

    // pass 1: scores for this warp's two heads
    for (int j = start + lane; j < end; j += 32) {
        int c = g_cols[j];
        float2 hr2 = *(const float2*)(g_hr + c * NHEAD + hp * 2);
        float e0 = hl2.x + hr2.x; e0 = e0 > 0.f ? e0 : ALPHA * e0;
        float e1 = hl2.y + hr2.y; e1 = e1 > 0.f ? e1 : ALPHA * e1;
        mx0 = fmaxf(mx0, e0);
        mx1 = fmaxf(mx1, e1);
        *(float2*)(g_escr + (size_t)j * NHEAD + hp * 2) = make_float2(e0, e1);
    }
#pragma unroll
    for (int o = 16; o; o >>= 1) {
        mx0 = fmaxf(mx0, __shfl_xor_sync(0xffffffffu, mx0, o));
        mx1 = fmaxf(mx1, __shfl_xor_sync(0xffffffffu, mx1, o));
    }
    __syncwarp();
    int head_local = lane >> 4;              // lanes 0-15 -> head hp*2, 16-31 -> hp*2+1
    float mxh = head_local ? mx1 : mx0;

    // pass 2: exp, denom, gather-accumulate (depth-1 pipeline)
    float den = 0.f;
    float4 acc = make_float4(0.f, 0.f, 0.f, 0.f);
    int c = g_cols[start];
    float2 e2 = *(const float2*)(g_escr + (size_t)start * NHEAD + hp * 2);
    float4 a = *(const float4*)(g_h + (size_t)c * FEAT + hp * 128 + lane * 4);
    for (int j = start; j < end; j++) {
        float4 ca = a;
        float2 ce = e2;
        if (j + 1 < end) {
            int cn = g_cols[j + 1];
            e2 = *(const float2*)(g_escr + (size_t)(j + 1) * NHEAD + hp * 2);
            a = *(const float4*)(g_h + (size_t)cn * FEAT + hp * 128 + lane * 4);
        }
        float eh = head_local ? ce.y : ce.x;
        float ee = __expf(eh - mxh);
        den += ee;
        acc.x = fmaf(ee, ca.x, acc.x);
        acc.y = fmaf(ee, ca.y, acc.y);
        acc.z = fmaf(ee, ca.z, acc.z);
        acc.w = fmaf(ee, ca.w, acc.w);
    }
    float inv = 1.0f / den;
    *(float4*)orow = make_float4(acc.x * inv, acc.y * inv, acc.z * inv, acc.w * inv);
}

// ================= launch =================
extern "C" void kernel_launch(void* const* d_in, const int* in_sizes, int n_in,
                              void* d_out, int out_size) {
    const float* x  = (const float*)d_in[0];
    const int*   eg = (const int*)d_in[1];
    const float* W  = (const float*)d_in[2];
    const float* al = (const float*)d_in[3];
    const float* ar = (const float*)d_in[4];
    float* out = (float*)d_out;

    cudaFuncSetAttribute(gemm_tf32_kernel, cudaFuncAttributeMaxDynamicSharedMemorySize,
                         GEMM_SMEM_BYTES);

    // Order chosen so the fixed ncu skip-window (lands on launch #4) captures the GEMM.
    zero_deg_kernel<<<(NN + 255) / 256, 256>>>();
    hist_kernel<<<(EE + 255) / 256, 256>>>(eg);
    scan_kernel<<<1, 1024>>>();

    dim3 ggrid(FEAT / 64, (NN + 127) / 128);
    gemm_tf32_kernel<<<ggrid, 128, GEMM_SMEM_BYTES>>>(x, W);

    scatter_kernel<<<(EE + 255) / 256, 256>>>(eg);
    logits_kernel<<<(NN * 32 + 255) / 256, 256>>>(al, ar);

    int agg_warps = NN * 2;
    aggregate_kernel<<<(agg_warps * 32 + 255) / 256, 256>>>(out);
}

// round 4
// speedup vs baseline: 1.1861x; 1.0390x over previous
#include <cuda_runtime.h>
#include <cuda_bf16.h>
#include <math_constants.h>

#define NN   50000
#define EE   800000
#define INF_ 256
#define OUTF 64
#define NHEAD 4
#define FEAT (NHEAD*OUTF)   // 256
#define ALPHA 0.2f

// -------- device scratch (static; allocation-free) --------
__device__ float g_h[(size_t)NN * FEAT];
__device__ float g_hl[NN * NHEAD];
__device__ float g_hr[NN * NHEAD];
__device__ int   g_deg[NN];
__device__ int   g_rowptr[NN + 1];
__device__ int   g_cursor[NN];
__device__ int   g_cols[EE];

// ====================== tf32 tensor-core GEMM: H = X @ W ======================
// Block 128x64, BK=32, 256 threads = 8 warps (4M x 2N), warp tile 32x32.
// Fragment-major smem (conflict-free LDS.128 A frags / LDS.64 B frags):
//  A: elem(r,k) -> kk=k>>3 (stride 1064), rgrp=r>>4 (stride 128), g=r&7 (16),
//     tg=k&3 (4), slot = ((r>>3)&1) + 2*((k>>2)&1)
//  B: elem(k,n) -> kk=k>>3 (stride 520), n (stride 8), p = 2*(k&3)+((k>>2)&1)
// Epilogue additionally computes hl/hr for this block's head (block-col == head).
#define A_STAGE 4256   // floats
#define B_STAGE 2080   // floats
#define GEMM_SMEM_BYTES ((2*A_STAGE + 2*B_STAGE)*4)

__device__ __forceinline__ float f2tf32(float x) {
    unsigned r;
    asm("cvt.rna.tf32.f32 %0, %1;" : "=r"(r) : "f"(x));
    return __uint_as_float(r);
}

__device__ __forceinline__ void mma_tf32(float c[4], float a0, float a1, float a2,
                                         float a3, float b0, float b1) {
    asm volatile(
        "mma.sync.aligned.m16n8k8.row.col.f32.tf32.tf32.f32 "
        "{%0,%1,%2,%3}, {%4,%5,%6,%7}, {%8,%9}, {%0,%1,%2,%3};"
        : "+f"(c[0]), "+f"(c[1]), "+f"(c[2]), "+f"(c[3])
        : "r"(__float_as_uint(a0)), "r"(__float_as_uint(a1)),
          "r"(__float_as_uint(a2)), "r"(__float_as_uint(a3)),
          "r"(__float_as_uint(b0)), "r"(__float_as_uint(b1)));
}

__global__ __launch_bounds__(256, 2) void gemm_tf32_kernel(
    const float* __restrict__ X, const float* __restrict__ W,
    const float* __restrict__ al, const float* __restrict__ ar) {
    extern __shared__ float smem[];
    float* sA = smem;                  // [2][A_STAGE]
    float* sB = smem + 2 * A_STAGE;    // [2][B_STAGE]
    int tid = threadIdx.x;
    int lane = tid & 31;
    int wid = tid >> 5;
    int wm = wid >> 1, wn = wid & 1;   // 4 M-warps x 2 N-warps
    int g = lane >> 2, tg = lane & 3;
    int bm = blockIdx.y * 128;
    int bn = blockIdx.x * 64;
    int hb = blockIdx.x;               // head index (64 cols per head)

    float acc[2][4][4];
#pragma unroll
    for (int mt = 0; mt < 2; mt++)
#pragma unroll
        for (int nt = 0; nt < 4; nt++)
#pragma unroll
            for (int q = 0; q < 4; q++) acc[mt][nt][q] = 0.f;

    float4 ra[4];
    float4 rb[2];

    // ---- prologue: load tile 0 ----
#pragma unroll
    for (int i = 0; i < 4; i++) {
        int f = tid + i * 256;
        int r = f >> 3, c4 = (f & 7) * 4;
        int row = bm + r;
        ra[i] = (row < NN) ? *(const float4*)(X + (size_t)row * INF_ + c4)
                           : make_float4(0.f, 0.f, 0.f, 0.f);
    }
#pragma unroll
    for (int i = 0; i < 2; i++) {
        int f = tid + i * 256;
        int kr = f & 31, nn = (f >> 5) * 4;
        rb[i] = *(const float4*)(W + (size_t)kr * FEAT + bn + nn);
    }
#pragma unroll
    for (int i = 0; i < 4; i++) {
        int f = tid + i * 256;
        int r = f >> 3, c4 = (f & 7) * 4;
        float* p = sA + (c4 >> 3) * 1064 + (r >> 4) * 128 + (r & 7) * 16 +
                   ((r >> 3) & 1) + 2 * ((c4 >> 2) & 1);
        p[0]  = f2tf32(ra[i].x);
        p[4]  = f2tf32(ra[i].y);
        p[8]  = f2tf32(ra[i].z);
        p[12] = f2tf32(ra[i].w);
    }
#pragma unroll
    for (int i = 0; i < 2; i++) {
        int f = tid + i * 256;
        int kr = f & 31, nn = (f >> 5) * 4;
        float* q = sB + (kr >> 3) * 520 + nn * 8 + 2 * (kr & 3) + ((kr >> 2) & 1);
        q[0]  = f2tf32(rb[i].x);
        q[8]  = f2tf32(rb[i].y);
        q[16] = f2tf32(rb[i].z);
        q[24] = f2tf32(rb[i].w);
    }
    __syncthreads();

    for (int kt = 0; kt < 8; kt++) {
        int st = kt & 1;
        if (kt < 7) {
            int k0 = (kt + 1) * 32;
#pragma unroll
            for (int i = 0; i < 4; i++) {
                int f = tid + i * 256;
                int r = f >> 3, c4 = (f & 7) * 4;
                int row = bm + r;
                ra[i] = (row < NN) ? *(const float4*)(X + (size_t)row * INF_ + k0 + c4)
                                   : make_float4(0.f, 0.f, 0.f, 0.f);
            }
#pragma unroll
            for (int i = 0; i < 2; i++) {
                int f = tid + i * 256;
                int kr = f & 31, nn = (f >> 5) * 4;
                rb[i] = *(const float4*)(W + (size_t)(k0 + kr) * FEAT + bn + nn);
            }
        }
        {
            const float* As = sA + st * A_STAGE;
            const float* Bs = sB + st * B_STAGE;
#pragma unroll
            for (int kk = 0; kk < 4; kk++) {
                float4 afr[2];
                float2 bfr[4];
#pragma unroll
                for (int mt = 0; mt < 2; mt++)
                    afr[mt] = *(const float4*)(As + kk * 1064 + (wm * 2 + mt) * 128 +
                                               g * 16 + tg * 4);
#pragma unroll
                for (int nt = 0; nt < 4; nt++)
                    bfr[nt] = *(const float2*)(Bs + kk * 520 + (wn * 32 + nt * 8 + g) * 8 +
                                               tg * 2);
#pragma unroll
                for (int mt = 0; mt < 2; mt++)
#pragma unroll
                    for (int nt = 0; nt < 4; nt++)
                        mma_tf32(acc[mt][nt], afr[mt].x, afr[mt].y, afr[mt].z, afr[mt].w,
                                 bfr[nt].x, bfr[nt].y);
            }
        }
        if (kt < 7) {
            float* dA = sA + (1 - st) * A_STAGE;
            float* dB = sB + (1 - st) * B_STAGE;
#pragma unroll
            for (int i = 0; i < 4; i++) {
                int f = tid + i * 256;
                int r = f >> 3, c4 = (f & 7) * 4;
                float* p = dA + (c4 >> 3) * 1064 + (r >> 4) * 128 + (r & 7) * 16 +
                           ((r >> 3) & 1) + 2 * ((c4 >> 2) & 1);
                p[0]  = f2tf32(ra[i].x);
                p[4]  = f2tf32(ra[i].y);
                p[8]  = f2tf32(ra[i].z);
                p[12] = f2tf32(ra[i].w);
            }
#pragma unroll
            for (int i = 0; i < 2; i++) {
                int f = tid + i * 256;
                int kr = f & 31, nn = (f >> 5) * 4;
                float* q = dB + (kr >> 3) * 520 + nn * 8 + 2 * (kr & 3) + ((kr >> 2) & 1);
                q[0]  = f2tf32(rb[i].x);
                q[8]  = f2tf32(rb[i].y);
                q[16] = f2tf32(rb[i].z);
                q[24] = f2tf32(rb[i].w);
            }
        }
        __syncthreads();
    }

    // ---- epilogue: store h, plus fused hl/hr logits for this head ----
    const float* alh = al + hb * OUTF;
    const float* arh = ar + hb * OUTF;
    float plv[2][2] = {{0.f, 0.f}, {0.f, 0.f}};
    float prv[2][2] = {{0.f, 0.f}, {0.f, 0.f}};

#pragma unroll
    for (int mt = 0; mt < 2; mt++) {
#pragma unroll
        for (int nt = 0; nt < 4; nt++) {
            int row0 = bm + wm * 32 + mt * 16 + g;
            int cl = wn * 32 + nt * 8 + tg * 2;     // col local to head
            int col = bn + cl;
            if (row0 < NN)
                *(float2*)(g_h + (size_t)row0 * FEAT + col) =
                    make_float2(acc[mt][nt][0], acc[mt][nt][1]);
            if (row0 + 8 < NN)
                *(float2*)(g_h + (size_t)(row0 + 8) * FEAT + col) =
                    make_float2(acc[mt][nt][2], acc[mt][nt][3]);
            float a0l = alh[cl], a1l = alh[cl + 1];
            float a0r = arh[cl], a1r = arh[cl + 1];
            plv[mt][0] = fmaf(a0l, acc[mt][nt][0], fmaf(a1l, acc[mt][nt][1], plv[mt][0]));
            plv[mt][1] = fmaf(a0l, acc[mt][nt][2], fmaf(a1l, acc[mt][nt][3], plv[mt][1]));
            prv[mt][0] = fmaf(a0r, acc[mt][nt][0], fmaf(a1r, acc[mt][nt][1], prv[mt][0]));
            prv[mt][1] = fmaf(a0r, acc[mt][nt][2], fmaf(a1r, acc[mt][nt][3], prv[mt][1]));
        }
    }
    // reduce over tg (lanes 0..3 within each g-group)
#pragma unroll
    for (int off = 1; off < 4; off <<= 1) {
#pragma unroll
        for (int mt = 0; mt < 2; mt++)
#pragma unroll
            for (int rh = 0; rh < 2; rh++) {
                plv[mt][rh] += __shfl_xor_sync(0xffffffffu, plv[mt][rh], off);
                prv[mt][rh] += __shfl_xor_sync(0xffffffffu, prv[mt][rh], off);
            }
    }
    __syncthreads();   // done with sA/sB; reuse smem for partials
    float* sPL = smem;         // [2][128]
    float* sPR = smem + 256;   // [2][128]
    if (tg == 0) {
#pragma unroll
        for (int mt = 0; mt < 2; mt++)
#pragma unroll
            for (int rh = 0; rh < 2; rh++) {
                int rowl = wm * 32 + mt * 16 + rh * 8 + g;
                sPL[wn * 128 + rowl] = plv[mt][rh];
                sPR[wn * 128 + rowl] = prv[mt][rh];
            }
    }
    __syncthreads();
    if (tid < 128) {
        int row = bm + tid;
        if (row < NN) {
            g_hl[row * NHEAD + hb] = sPL[tid] + sPL[128 + tid];
            g_hr[row * NHEAD + hb] = sPR[tid] + sPR[128 + tid];
        }
    }
}

// ============== CSR build ==============
__global__ void zero_deg_kernel() {
    int i = blockIdx.x * blockDim.x + threadIdx.x;
    if (i < NN) g_deg[i] = 0;
}

__global__ void hist_kernel(const int* __restrict__ edge) {
    int e = blockIdx.x * blockDim.x + threadIdx.x;
    if (e < EE) atomicAdd(&g_deg[edge[e]], 1);
}

__global__ __launch_bounds__(1024) void scan_kernel() {
    __shared__ int warp_sums[32];
    __shared__ int s_carry;
    int tid = threadIdx.x;
    int lane = tid & 31, w = tid >> 5;
    if (tid == 0) { s_carry = 0; g_rowptr[0] = 0; }
    __syncthreads();
    for (int base = 0; base < NN; base += 8192) {
        int i0 = base + tid * 8;
        int v[8];
#pragma unroll
        for (int j = 0; j < 8; j++) {
            int i = i0 + j;
            v[j] = (i < NN) ? g_deg[i] : 0;
        }
#pragma unroll
        for (int j = 1; j < 8; j++) v[j] += v[j - 1];
        int x = v[7];
#pragma unroll
        for (int o = 1; o < 32; o <<= 1) {
            int y = __shfl_up_sync(0xffffffffu, x, o);
            if (lane >= o) x += y;
        }
        if (lane == 31) warp_sums[w] = x;
        __syncthreads();
        if (w == 0) {
            int s = warp_sums[lane];
#pragma unroll
            for (int o = 1; o < 32; o <<= 1) {
                int y = __shfl_up_sync(0xffffffffu, s, o);
                if (lane >= o) s += y;
            }
            warp_sums[lane] = s;
        }
        __syncthreads();
        int off = (x - v[7]) + (w > 0 ? warp_sums[w - 1] : 0) + s_carry;
#pragma unroll
        for (int j = 0; j < 8; j++) {
            int i = i0 + j;
            if (i < NN) {
                g_rowptr[i + 1] = off + v[j];
                g_cursor[i] = off + (j > 0 ? v[j - 1] : 0);
            }
        }
        __syncthreads();
        if (tid == 0) s_carry += warp_sums[31];
        __syncthreads();
    }
}

__global__ void scatter_kernel(const int* __restrict__ edge) {
    int e = blockIdx.x * blockDim.x + threadIdx.x;
    if (e < EE) {
        int r = edge[e];
        int c = edge[EE + e];
        int pos = atomicAdd(&g_cursor[r], 1);
        g_cols[pos] = c;
    }
}

// ============== SINGLE-PASS fused softmax + SpMM ==============
// exp(e)/sum(exp(e)) == exp(e-max)/sum(exp(e-max)); scores are O(10) so no max
// subtraction is needed for fp32 stability. One pass: no score scratch array.
// Warp = (row, head-pair hp); lane owns 4 feats; lanes 0-15 head hp*2, 16-31 hp*2+1.
__global__ __launch_bounds__(256) void aggregate_kernel(float* __restrict__ out) {
    int gw = (blockIdx.x * blockDim.x + threadIdx.x) >> 5;
    int lane = threadIdx.x & 31;
    int row = gw >> 1;
    int hp = gw & 1;
    if (row >= NN) return;
    int start = g_rowptr[row];
    int end = g_rowptr[row + 1];
    float* orow = out + (size_t)row * FEAT + hp * 128 + lane * 4;
    if (start == end) {
        *(float4*)orow = make_float4(0.f, 0.f, 0.f, 0.f);
        return;
    }
    float2 hl2 = *(const float2*)(g_hl + row * NHEAD + hp * 2);
    int head_local = lane >> 4;
    float hlv = head_local ? hl2.y : hl2.x;

    float den = 0.f;
    float4 acc = make_float4(0.f, 0.f, 0.f, 0.f);

    // depth-1 data pipeline; cols prefetched one level deeper
    int c0 = g_cols[start];
    int c1 = (start + 1 < end) ? g_cols[start + 1] : c0;
    float2 hr = *(const float2*)(g_hr + c0 * NHEAD + hp * 2);
    float4 hv = *(const float4*)(g_h + (size_t)c0 * FEAT + hp * 128 + lane * 4);
    for (int j = start; j < end; j++) {
        float2 hrc = hr;
        float4 hvc = hv;
        int c2 = (j + 2 < end) ? g_cols[j + 2] : c1;
        if (j + 1 < end) {
            hr = *(const float2*)(g_hr + c1 * NHEAD + hp * 2);
            hv = *(const float4*)(g_h + (size_t)c1 * FEAT + hp * 128 + lane * 4);
        }
        c1 = c2;
        float e = hlv + (head_local ? hrc.y : hrc.x);
        e = e > 0.f ? e : ALPHA * e;
        float ee = __expf(e);
        den += ee;
        acc.x = fmaf(ee, hvc.x, acc.x);
        acc.y = fmaf(ee, hvc.y, acc.y);
        acc.z = fmaf(ee, hvc.z, acc.z);
        acc.w = fmaf(ee, hvc.w, acc.w);
    }
    float inv = 1.0f / den;
    *(float4*)orow = make_float4(acc.x * inv, acc.y * inv, acc.z * inv, acc.w * inv);
}

// ================= launch =================
extern "C" void kernel_launch(void* const* d_in, const int* in_sizes, int n_in,
                              void* d_out, int out_size) {
    const float* x  = (const float*)d_in[0];
    const int*   eg = (const int*)d_in[1];
    const float* W  = (const float*)d_in[2];
    const float* al = (const float*)d_in[3];
    const float* ar = (const float*)d_in[4];
    float* out = (float*)d_out;

    cudaFuncSetAttribute(gemm_tf32_kernel, cudaFuncAttributeMaxDynamicSharedMemorySize,
                         GEMM_SMEM_BYTES);

    // Order: ncu capture window lands on launch #4 -> gemm stays visible.
    zero_deg_kernel<<<(NN + 255) / 256, 256>>>();
    hist_kernel<<<(EE + 255) / 256, 256>>>(eg);
    scan_kernel<<<1, 1024>>>();

    dim3 ggrid(FEAT / 64, (NN + 127) / 128);
    gemm_tf32_kernel<<<ggrid, 256, GEMM_SMEM_BYTES>>>(x, W, al, ar);

    scatter_kernel<<<(EE + 255) / 256, 256>>>(eg);

    int agg_warps = NN * 2;
    aggregate_kernel<<<(agg_warps * 32 + 255) / 256, 256>>>(out);
}

// round 6
// speedup vs baseline: 1.2615x; 1.0636x over previous
#include <cuda_runtime.h>
#include <cuda_fp16.h>
#include <math_constants.h>
#include <cstdint>

#define NN   50000
#define EE   800000
#define INF_ 256
#define OUTF 64
#define NHEAD 4
#define FEAT (NHEAD*OUTF)   // 256
#define ALPHA 0.2f

// -------- device scratch (static; allocation-free) --------
__device__ __half g_hh[(size_t)NN * FEAT];   // projected features, fp16
__device__ float g_hl[NN * NHEAD];
__device__ float g_hr[NN * NHEAD];
__device__ int   g_deg[NN];
__device__ int   g_rowptr[NN + 1];
__device__ int   g_cursor[NN];
__device__ int   g_cols[EE];

// ====================== tf32 mma.sync GEMM: H = X @ W ======================
// Block 128x64, BK=32, 128 threads = 4 warps (2M x 2N), warp tile 64x32.
// Fragment-major smem (conflict-free LDS.128 A frags / LDS.64 B frags).
// Epilogue: h stored as fp16; fused per-head hl/hr logits (block-col == head).
#define A_STAGE 4256   // floats
#define B_STAGE 2080   // floats
#define GEMM_SMEM_BYTES ((2*A_STAGE + 2*B_STAGE)*4)

__device__ __forceinline__ float f2tf32(float x) {
    unsigned r;
    asm("cvt.rna.tf32.f32 %0, %1;" : "=r"(r) : "f"(x));
    return __uint_as_float(r);
}

__device__ __forceinline__ void mma_tf32(float c[4], float a0, float a1, float a2,
                                         float a3, float b0, float b1) {
    asm volatile(
        "mma.sync.aligned.m16n8k8.row.col.f32.tf32.tf32.f32 "
        "{%0,%1,%2,%3}, {%4,%5,%6,%7}, {%8,%9}, {%0,%1,%2,%3};"
        : "+f"(c[0]), "+f"(c[1]), "+f"(c[2]), "+f"(c[3])
        : "r"(__float_as_uint(a0)), "r"(__float_as_uint(a1)),
          "r"(__float_as_uint(a2)), "r"(__float_as_uint(a3)),
          "r"(__float_as_uint(b0)), "r"(__float_as_uint(b1)));
}

__global__ __launch_bounds__(128) void gemm_tf32_kernel(
    const float* __restrict__ X, const float* __restrict__ W,
    const float* __restrict__ al, const float* __restrict__ ar) {
    extern __shared__ float smem[];
    float* sA = smem;
    float* sB = smem + 2 * A_STAGE;
    int tid = threadIdx.x;
    int lane = tid & 31;
    int wid = tid >> 5;
    int wm = wid >> 1, wn = wid & 1;
    int g = lane >> 2, tg = lane & 3;
    int bm = blockIdx.y * 128;
    int bn = blockIdx.x * 64;
    int hb = blockIdx.x;               // head (64 cols per head)

    float acc[4][4][4];
#pragma unroll
    for (int mt = 0; mt < 4; mt++)
#pragma unroll
        for (int nt = 0; nt < 4; nt++)
#pragma unroll
            for (int q = 0; q < 4; q++) acc[mt][nt][q] = 0.f;

    float4 ra[8];
    float4 rb[4];

    // prologue: tile 0
#pragma unroll
    for (int i = 0; i < 8; i++) {
        int f = tid + i * 128;
        int r = f >> 3, c4 = (f & 7) * 4;
        int row = bm + r;
        ra[i] = (row < NN) ? *(const float4*)(X + (size_t)row * INF_ + c4)
                           : make_float4(0.f, 0.f, 0.f, 0.f);
    }
#pragma unroll
    for (int i = 0; i < 4; i++) {
        int f = tid + i * 128;
        int kr = f & 31, nn = (f >> 5) * 4;
        rb[i] = *(const float4*)(W + (size_t)kr * FEAT + bn + nn);
    }
#pragma unroll
    for (int i = 0; i < 8; i++) {
        int f = tid + i * 128;
        int r = f >> 3, c4 = (f & 7) * 4;
        float* p = sA + (c4 >> 3) * 1064 + (r >> 4) * 128 + (r & 7) * 16 +
                   ((r >> 3) & 1) + 2 * ((c4 >> 2) & 1);
        p[0]  = f2tf32(ra[i].x);
        p[4]  = f2tf32(ra[i].y);
        p[8]  = f2tf32(ra[i].z);
        p[12] = f2tf32(ra[i].w);
    }
#pragma unroll
    for (int i = 0; i < 4; i++) {
        int f = tid + i * 128;
        int kr = f & 31, nn = (f >> 5) * 4;
        float* q = sB + (kr >> 3) * 520 + nn * 8 + 2 * (kr & 3) + ((kr >> 2) & 1);
        q[0]  = f2tf32(rb[i].x);
        q[8]  = f2tf32(rb[i].y);
        q[16] = f2tf32(rb[i].z);
        q[24] = f2tf32(rb[i].w);
    }
    __syncthreads();

    for (int kt = 0; kt < 8; kt++) {
        int st = kt & 1;
        if (kt < 7) {
            int k0 = (kt + 1) * 32;
#pragma unroll
            for (int i = 0; i < 8; i++) {
                int f = tid + i * 128;
                int r = f >> 3, c4 = (f & 7) * 4;
                int row = bm + r;
                ra[i] = (row < NN) ? *(const float4*)(X + (size_t)row * INF_ + k0 + c4)
                                   : make_float4(0.f, 0.f, 0.f, 0.f);
            }
#pragma unroll
            for (int i = 0; i < 4; i++) {
                int f = tid + i * 128;
                int kr = f & 31, nn = (f >> 5) * 4;
                rb[i] = *(const float4*)(W + (size_t)(k0 + kr) * FEAT + bn + nn);
            }
        }
        {
            const float* As = sA + st * A_STAGE;
            const float* Bs = sB + st * B_STAGE;
#pragma unroll
            for (int kk = 0; kk < 4; kk++) {
                float4 afr[4];
                float2 bfr[4];
#pragma unroll
                for (int mt = 0; mt < 4; mt++)
                    afr[mt] = *(const float4*)(As + kk * 1064 + (wm * 4 + mt) * 128 +
                                               g * 16 + tg * 4);
#pragma unroll
                for (int nt = 0; nt < 4; nt++)
                    bfr[nt] = *(const float2*)(Bs + kk * 520 + (wn * 32 + nt * 8 + g) * 8 +
                                               tg * 2);
#pragma unroll
                for (int mt = 0; mt < 4; mt++)
#pragma unroll
                    for (int nt = 0; nt < 4; nt++)
                        mma_tf32(acc[mt][nt], afr[mt].x, afr[mt].y, afr[mt].z, afr[mt].w,
                                 bfr[nt].x, bfr[nt].y);
            }
        }
        if (kt < 7) {
            float* dA = sA + (1 - st) * A_STAGE;
            float* dB = sB + (1 - st) * B_STAGE;
#pragma unroll
            for (int i = 0; i < 8; i++) {
                int f = tid + i * 128;
                int r = f >> 3, c4 = (f & 7) * 4;
                float* p = dA + (c4 >> 3) * 1064 + (r >> 4) * 128 + (r & 7) * 16 +
                           ((r >> 3) & 1) + 2 * ((c4 >> 2) & 1);
                p[0]  = f2tf32(ra[i].x);
                p[4]  = f2tf32(ra[i].y);
                p[8]  = f2tf32(ra[i].z);
                p[12] = f2tf32(ra[i].w);
            }
#pragma unroll
            for (int i = 0; i < 4; i++) {
                int f = tid + i * 128;
                int kr = f & 31, nn = (f >> 5) * 4;
                float* q = dB + (kr >> 3) * 520 + nn * 8 + 2 * (kr & 3) + ((kr >> 2) & 1);
                q[0]  = f2tf32(rb[i].x);
                q[8]  = f2tf32(rb[i].y);
                q[16] = f2tf32(rb[i].z);
                q[24] = f2tf32(rb[i].w);
            }
        }
        __syncthreads();
    }

    // ---- epilogue: store h as fp16; fused hl/hr logits for this head ----
    const float* alh = al + hb * OUTF;
    const float* arh = ar + hb * OUTF;
    float plv[4][2] = {{0.f,0.f},{0.f,0.f},{0.f,0.f},{0.f,0.f}};
    float prv[4][2] = {{0.f,0.f},{0.f,0.f},{0.f,0.f},{0.f,0.f}};

#pragma unroll
    for (int mt = 0; mt < 4; mt++) {
#pragma unroll
        for (int nt = 0; nt < 4; nt++) {
            int row0 = bm + wm * 64 + mt * 16 + g;
            int cl = wn * 32 + nt * 8 + tg * 2;
            int col = bn + cl;
            if (row0 < NN)
                *(__half2*)(g_hh + (size_t)row0 * FEAT + col) =
                    __floats2half2_rn(acc[mt][nt][0], acc[mt][nt][1]);
            if (row0 + 8 < NN)
                *(__half2*)(g_hh + (size_t)(row0 + 8) * FEAT + col) =
                    __floats2half2_rn(acc[mt][nt][2], acc[mt][nt][3]);
            float a0l = alh[cl], a1l = alh[cl + 1];
            float a0r = arh[cl], a1r = arh[cl + 1];
            plv[mt][0] = fmaf(a0l, acc[mt][nt][0], fmaf(a1l, acc[mt][nt][1], plv[mt][0]));
            plv[mt][1] = fmaf(a0l, acc[mt][nt][2], fmaf(a1l, acc[mt][nt][3], plv[mt][1]));
            prv[mt][0] = fmaf(a0r, acc[mt][nt][0], fmaf(a1r, acc[mt][nt][1], prv[mt][0]));
            prv[mt][1] = fmaf(a0r, acc[mt][nt][2], fmaf(a1r, acc[mt][nt][3], prv[mt][1]));
        }
    }
#pragma unroll
    for (int off = 1; off < 4; off <<= 1) {
#pragma unroll
        for (int mt = 0; mt < 4; mt++)
#pragma unroll
            for (int rh = 0; rh < 2; rh++) {
                plv[mt][rh] += __shfl_xor_sync(0xffffffffu, plv[mt][rh], off);
                prv[mt][rh] += __shfl_xor_sync(0xffffffffu, prv[mt][rh], off);
            }
    }
    __syncthreads();   // tiles dead; reuse smem
    float* sPL = smem;         // [2][128]
    float* sPR = smem + 256;
    if (tg == 0) {
#pragma unroll
        for (int mt = 0; mt < 4; mt++)
#pragma unroll
            for (int rh = 0; rh < 2; rh++) {
                int rowl = wm * 64 + mt * 16 + rh * 8 + g;
                sPL[wn * 128 + rowl] = plv[mt][rh];
                sPR[wn * 128 + rowl] = prv[mt][rh];
            }
    }
    __syncthreads();
    if (tid < 128) {
        int row = bm + tid;
        if (row < NN) {
            g_hl[row * NHEAD + hb] = sPL[tid] + sPL[128 + tid];
            g_hr[row * NHEAD + hb] = sPR[tid] + sPR[128 + tid];
        }
    }
}

// ============== CSR build ==============
__global__ void zero_deg_kernel() {
    int i = blockIdx.x * blockDim.x + threadIdx.x;
    if (i < NN) g_deg[i] = 0;
}

__global__ void hist_kernel(const int* __restrict__ edge) {
    int e = blockIdx.x * blockDim.x + threadIdx.x;
    if (e < EE) atomicAdd(&g_deg[edge[e]], 1);
}

__global__ __launch_bounds__(1024) void scan_kernel() {
    __shared__ int warp_sums[32];
    __shared__ int s_carry;
    int tid = threadIdx.x;
    int lane = tid & 31, w = tid >> 5;
    if (tid == 0) { s_carry = 0; g_rowptr[0] = 0; }
    __syncthreads();
    for (int base = 0; base < NN; base += 8192) {
        int i0 = base + tid * 8;
        int v[8];
#pragma unroll
        for (int j = 0; j < 8; j++) {
            int i = i0 + j;
            v[j] = (i < NN) ? g_deg[i] : 0;
        }
#pragma unroll
        for (int j = 1; j < 8; j++) v[j] += v[j - 1];
        int x = v[7];
#pragma unroll
        for (int o = 1; o < 32; o <<= 1) {
            int y = __shfl_up_sync(0xffffffffu, x, o);
            if (lane >= o) x += y;
        }
        if (lane == 31) warp_sums[w] = x;
        __syncthreads();
        if (w == 0) {
            int s = warp_sums[lane];
#pragma unroll
            for (int o = 1; o < 32; o <<= 1) {
                int y = __shfl_up_sync(0xffffffffu, s, o);
                if (lane >= o) s += y;
            }
            warp_sums[lane] = s;
        }
        __syncthreads();
        int off = (x - v[7]) + (w > 0 ? warp_sums[w - 1] : 0) + s_carry;
#pragma unroll
        for (int j = 0; j < 8; j++) {
            int i = i0 + j;
            if (i < NN) {
                g_rowptr[i + 1] = off + v[j];
                g_cursor[i] = off + (j > 0 ? v[j - 1] : 0);
            }
        }
        __syncthreads();
        if (tid == 0) s_carry += warp_sums[31];
        __syncthreads();
    }
}

__global__ void scatter_kernel(const int* __restrict__ edge) {
    int e = blockIdx.x * blockDim.x + threadIdx.x;
    if (e < EE) {
        int r = edge[e];
        int c = edge[EE + e];
        int pos = atomicAdd(&g_cursor[r], 1);
        g_cols[pos] = c;
    }
}

// ============== SINGLE-PASS fused softmax + SpMM (fp16 h gather) ==============
// Warp = (row, head-pair hp); lane owns 4 feats (8B fp16); lanes 0-15 head hp*2,
// 16-31 head hp*2+1. exp without max-shift (scores O(10), fp32-safe).
__global__ __launch_bounds__(256) void aggregate_kernel(float* __restrict__ out) {
    int gw = (blockIdx.x * blockDim.x + threadIdx.x) >> 5;
    int lane = threadIdx.x & 31;
    int row = gw >> 1;
    int hp = gw & 1;
    if (row >= NN) return;
    int start = g_rowptr[row];
    int end = g_rowptr[row + 1];
    float* orow = out + (size_t)row * FEAT + hp * 128 + lane * 4;
    if (start == end) {
        *(float4*)orow = make_float4(0.f, 0.f, 0.f, 0.f);
        return;
    }
    float2 hl2 = *(const float2*)(g_hl + row * NHEAD + hp * 2);
    int head_local = lane >> 4;
    float hlv = head_local ? hl2.y : hl2.x;

    float den = 0.f;
    float4 acc = make_float4(0.f, 0.f, 0.f, 0.f);

    const size_t fofs = hp * 128 + lane * 4;
    int c0 = g_cols[start];
    int c1 = (start + 1 < end) ? g_cols[start + 1] : c0;
    float2 hr = *(const float2*)(g_hr + c0 * NHEAD + hp * 2);
    float2 hv = *(const float2*)(g_hh + (size_t)c0 * FEAT + fofs);   // 4 halves
    for (int j = start; j < end; j++) {
        float2 hrc = hr;
        float2 hvc = hv;
        int c2 = (j + 2 < end) ? g_cols[j + 2] : c1;
        if (j + 1 < end) {
            hr = *(const float2*)(g_hr + c1 * NHEAD + hp * 2);
            hv = *(const float2*)(g_hh + (size_t)c1 * FEAT + fofs);
        }
        c1 = c2;
        float e = hlv + (head_local ? hrc.y : hrc.x);
        e = e > 0.f ? e : ALPHA * e;
        float ee = __expf(e);
        den += ee;
        __half2 p01 = *(__half2*)&hvc.x;
        __half2 p23 = *(__half2*)&hvc.y;
        float2 f01 = __half22float2(p01);
        float2 f23 = __half22float2(p23);
        acc.x = fmaf(ee, f01.x, acc.x);
        acc.y = fmaf(ee, f01.y, acc.y);
        acc.z = fmaf(ee, f23.x, acc.z);
        acc.w = fmaf(ee, f23.y, acc.w);
    }
    float inv = 1.0f / den;
    *(float4*)orow = make_float4(acc.x * inv, acc.y * inv, acc.z * inv, acc.w * inv);
}

// ================= launch =================
extern "C" void kernel_launch(void* const* d_in, const int* in_sizes, int n_in,
                              void* d_out, int out_size) {
    const float* x  = (const float*)d_in[0];
    const int*   eg = (const int*)d_in[1];
    const float* W  = (const float*)d_in[2];
    const float* al = (const float*)d_in[3];
    const float* ar = (const float*)d_in[4];
    float* out = (float*)d_out;

    cudaFuncSetAttribute(gemm_tf32_kernel, cudaFuncAttributeMaxDynamicSharedMemorySize,
                         GEMM_SMEM_BYTES);

    // ncu capture window lands on launch #4 -> gemm stays profiled.
    zero_deg_kernel<<<(NN + 255) / 256, 256>>>();
    hist_kernel<<<(EE + 255) / 256, 256>>>(eg);
    scan_kernel<<<1, 1024>>>();

    dim3 ggrid(FEAT / 64, (NN + 127) / 128);
    gemm_tf32_kernel<<<ggrid, 128, GEMM_SMEM_BYTES>>>(x, W, al, ar);

    scatter_kernel<<<(EE + 255) / 256, 256>>>(eg);

    int agg_warps = NN * 2;
    aggregate_kernel<<<(agg_warps * 32 + 255) / 256, 256>>>(out);
}

// round 7
// speedup vs baseline: 1.6557x; 1.3125x over previous
#include <cuda_runtime.h>
#include <cuda_fp16.h>
#include <math_constants.h>
#include <cstdint>

#define NN   50000
#define EE   800000
#define INF_ 256
#define OUTF 64
#define NHEAD 4
#define FEAT (NHEAD*OUTF)   // 256
#define ALPHA 0.2f

// -------- device scratch (static; allocation-free) --------
__device__ __half g_hh[(size_t)NN * FEAT];   // projected features, fp16
__device__ float g_hl[NN * NHEAD];
__device__ float g_hr[NN * NHEAD];
__device__ uint2 g_Wf[NHEAD * 16 * 8 * 32];  // W in fp16 mma-fragment order (128KB)
__device__ int   g_deg[NN];
__device__ int   g_rowptr[NN + 1];
__device__ int   g_cursor[NN];
__device__ int   g_cols[EE];

// ============ prep: pack W into fp16 B-fragments (per head/kstep/nblk/lane) ============
// B frag (m16n8k16, col): thread(g=lane>>2, tg=lane&3): b0={W[k0+2tg][n], W[k0+2tg+1][n]},
// b1 = same at k+8, with n = hb*64 + nblk*8 + g, k0 = ks*16.
__global__ void prep_wf_kernel(const float* __restrict__ W) {
    int idx = blockIdx.x * blockDim.x + threadIdx.x;
    if (idx >= NHEAD * 16 * 8 * 32) return;
    int lane = idx & 31;
    int nblk = (idx >> 5) & 7;
    int ks   = (idx >> 8) & 15;
    int hb   = idx >> 12;
    int g = lane >> 2, tg = lane & 3;
    int n = hb * OUTF + nblk * 8 + g;
    int k0 = ks * 16 + 2 * tg;
    __half2 b0 = __floats2half2_rn(W[(size_t)k0 * FEAT + n], W[(size_t)(k0 + 1) * FEAT + n]);
    __half2 b1 = __floats2half2_rn(W[(size_t)(k0 + 8) * FEAT + n], W[(size_t)(k0 + 9) * FEAT + n]);
    g_Wf[idx] = make_uint2(*(unsigned*)&b0, *(unsigned*)&b1);
}

// ====================== fp16 mma GEMM: H = X @ W ======================
// Block 128x64 (block-col == head), stage K=32, 128 threads = 4 warps (2M x 2N),
// warp tile 64x32, mma m16n8k16 (fp16 in, fp32 accum — same mantissa as tf32).
// A in smem, fragment-major: block(rgrp=r>>4 stride 512B, kst=k>>4 stride 4112B),
// lane vector 16B = {A[g][2tg..+1], A[g+8][2tg..+1], A[g][2tg+8..+9], A[g+8][2tg+8..+9]}
// -> compute-side fragment = one LDS.128, conflict-free (contiguous per 8 lanes).
// B fragments come straight from g_Wf (L2), prefetched one kstep ahead.
#define A_STAGE_B 8224   // bytes (2 kst * 4112)

__device__ __forceinline__ void mma_f16(float c[4], unsigned a0, unsigned a1,
                                        unsigned a2, unsigned a3,
                                        unsigned b0, unsigned b1) {
    asm volatile(
        "mma.sync.aligned.m16n8k16.row.col.f32.f16.f16.f32 "
        "{%0,%1,%2,%3}, {%4,%5,%6,%7}, {%8,%9}, {%0,%1,%2,%3};"
        : "+f"(c[0]), "+f"(c[1]), "+f"(c[2]), "+f"(c[3])
        : "r"(a0), "r"(a1), "r"(a2), "r"(a3), "r"(b0), "r"(b1));
}

__device__ __forceinline__ int a_sts_off(int r, int c4) {
    return ((c4 >> 4) ? 4112 : 0) + (r >> 4) * 512 +
           (((r & 7) * 4 + ((c4 & 7) >> 1)) << 4) + (((c4 >> 3) & 1) << 3) +
           (((r >> 3) & 1) << 2);
}

__global__ __launch_bounds__(128) void gemm_fp16_kernel(
    const float* __restrict__ X,
    const float* __restrict__ al, const float* __restrict__ ar) {
    __shared__ __align__(16) char sAbuf[2 * A_STAGE_B];
    int tid = threadIdx.x;
    int lane = tid & 31;
    int wid = tid >> 5;
    int wm = wid >> 1, wn = wid & 1;
    int g = lane >> 2, tg = lane & 3;
    int bm = blockIdx.y * 128;
    int hb = blockIdx.x;               // head
    int bn = hb * OUTF;

    float acc[4][4][4];
#pragma unroll
    for (int mt = 0; mt < 4; mt++)
#pragma unroll
        for (int nt = 0; nt < 4; nt++)
#pragma unroll
            for (int q = 0; q < 4; q++) acc[mt][nt][q] = 0.f;

    const uint2* Wfb = g_Wf + hb * (16 * 8 * 32);

    float4 ra[8];
    // prologue: A stage 0
#pragma unroll
    for (int i = 0; i < 8; i++) {
        int f = tid + i * 128;
        int r = f >> 3, c4 = (f & 7) * 4;
        int row = bm + r;
        ra[i] = (row < NN) ? *(const float4*)(X + (size_t)row * INF_ + c4)
                           : make_float4(0.f, 0.f, 0.f, 0.f);
    }
#pragma unroll
    for (int i = 0; i < 8; i++) {
        int f = tid + i * 128;
        int r = f >> 3, c4 = (f & 7) * 4;
        char* p = sAbuf + a_sts_off(r, c4);
        *(__half2*)p = __floats2half2_rn(ra[i].x, ra[i].y);
        *(__half2*)(p + 16) = __floats2half2_rn(ra[i].z, ra[i].w);
    }
    // B prefetch ks=0
    uint2 bq[4], bqn[4];
#pragma unroll
    for (int nt = 0; nt < 4; nt++)
        bq[nt] = Wfb[(0 * 8 + wn * 4 + nt) * 32 + lane];
    __syncthreads();

    for (int kt = 0; kt < 8; kt++) {
        int st = kt & 1;
        const char* As = sAbuf + st * A_STAGE_B;
        if (kt < 7) {
            int k0 = (kt + 1) * 32;
#pragma unroll
            for (int i = 0; i < 8; i++) {
                int f = tid + i * 128;
                int r = f >> 3, c4 = (f & 7) * 4;
                int row = bm + r;
                ra[i] = (row < NN) ? *(const float4*)(X + (size_t)row * INF_ + k0 + c4)
                                   : make_float4(0.f, 0.f, 0.f, 0.f);
            }
        }
#pragma unroll
        for (int kst = 0; kst < 2; kst++) {
            int ks = kt * 2 + kst;
            if (ks < 15) {
#pragma unroll
                for (int nt = 0; nt < 4; nt++)
                    bqn[nt] = Wfb[((ks + 1) * 8 + wn * 4 + nt) * 32 + lane];
            }
            uint4 af[4];
#pragma unroll
            for (int mt = 0; mt < 4; mt++)
                af[mt] = *(const uint4*)(As + kst * 4112 + (wm * 4 + mt) * 512 +
                                         (g * 4 + tg) * 16);
#pragma unroll
            for (int mt = 0; mt < 4; mt++)
#pragma unroll
                for (int nt = 0; nt < 4; nt++)
                    mma_f16(acc[mt][nt], af[mt].x, af[mt].y, af[mt].z, af[mt].w,
                            bq[nt].x, bq[nt].y);
#pragma unroll
            for (int nt = 0; nt < 4; nt++) bq[nt] = bqn[nt];
        }
        if (kt < 7) {
            char* dA = sAbuf + (1 - st) * A_STAGE_B;
#pragma unroll
            for (int i = 0; i < 8; i++) {
                int f = tid + i * 128;
                int r = f >> 3, c4 = (f & 7) * 4;
                char* p = dA + a_sts_off(r, c4);
                *(__half2*)p = __floats2half2_rn(ra[i].x, ra[i].y);
                *(__half2*)(p + 16) = __floats2half2_rn(ra[i].z, ra[i].w);
            }
        }
        __syncthreads();
    }

    // ---- epilogue: store h fp16; fused hl/hr logits for this head ----
    const float* alh = al + hb * OUTF;
    const float* arh = ar + hb * OUTF;
    float plv[4][2] = {{0.f,0.f},{0.f,0.f},{0.f,0.f},{0.f,0.f}};
    float prv[4][2] = {{0.f,0.f},{0.f,0.f},{0.f,0.f},{0.f,0.f}};

#pragma unroll
    for (int mt = 0; mt < 4; mt++) {
#pragma unroll
        for (int nt = 0; nt < 4; nt++) {
            int row0 = bm + wm * 64 + mt * 16 + g;
            int cl = wn * 32 + nt * 8 + tg * 2;
            int col = bn + cl;
            if (row0 < NN)
                *(__half2*)(g_hh + (size_t)row0 * FEAT + col) =
                    __floats2half2_rn(acc[mt][nt][0], acc[mt][nt][1]);
            if (row0 + 8 < NN)
                *(__half2*)(g_hh + (size_t)(row0 + 8) * FEAT + col) =
                    __floats2half2_rn(acc[mt][nt][2], acc[mt][nt][3]);
            float a0l = alh[cl], a1l = alh[cl + 1];
            float a0r = arh[cl], a1r = arh[cl + 1];
            plv[mt][0] = fmaf(a0l, acc[mt][nt][0], fmaf(a1l, acc[mt][nt][1], plv[mt][0]));
            plv[mt][1] = fmaf(a0l, acc[mt][nt][2], fmaf(a1l, acc[mt][nt][3], plv[mt][1]));
            prv[mt][0] = fmaf(a0r, acc[mt][nt][0], fmaf(a1r, acc[mt][nt][1], prv[mt][0]));
            prv[mt][1] = fmaf(a0r, acc[mt][nt][2], fmaf(a1r, acc[mt][nt][3], prv[mt][1]));
        }
    }
#pragma unroll
    for (int off = 1; off < 4; off <<= 1) {
#pragma unroll
        for (int mt = 0; mt < 4; mt++)
#pragma unroll
            for (int rh = 0; rh < 2; rh++) {
                plv[mt][rh] += __shfl_xor_sync(0xffffffffu, plv[mt][rh], off);
                prv[mt][rh] += __shfl_xor_sync(0xffffffffu, prv[mt][rh], off);
            }
    }
    __syncthreads();
    float* sPL = (float*)sAbuf;          // [2][128]
    float* sPR = (float*)sAbuf + 256;
    if (tg == 0) {
#pragma unroll
        for (int mt = 0; mt < 4; mt++)
#pragma unroll
            for (int rh = 0; rh < 2; rh++) {
                int rowl = wm * 64 + mt * 16 + rh * 8 + g;
                sPL[wn * 128 + rowl] = plv[mt][rh];
                sPR[wn * 128 + rowl] = prv[mt][rh];
            }
    }
    __syncthreads();
    if (tid < 128) {
        int row = bm + tid;
        if (row < NN) {
            g_hl[row * NHEAD + hb] = sPL[tid] + sPL[128 + tid];
            g_hr[row * NHEAD + hb] = sPR[tid] + sPR[128 + tid];
        }
    }
}

// ============== CSR build ==============
__global__ void zero_deg_kernel() {
    int i = blockIdx.x * blockDim.x + threadIdx.x;
    if (i < NN) g_deg[i] = 0;
}

__global__ void hist_kernel(const int* __restrict__ edge) {
    int e = blockIdx.x * blockDim.x + threadIdx.x;
    if (e < EE) atomicAdd(&g_deg[edge[e]], 1);
}

__global__ __launch_bounds__(1024) void scan_kernel() {
    __shared__ int warp_sums[32];
    __shared__ int s_carry;
    int tid = threadIdx.x;
    int lane = tid & 31, w = tid >> 5;
    if (tid == 0) { s_carry = 0; g_rowptr[0] = 0; }
    __syncthreads();
    for (int base = 0; base < NN; base += 8192) {
        int i0 = base + tid * 8;
        int v[8];
#pragma unroll
        for (int j = 0; j < 8; j++) {
            int i = i0 + j;
            v[j] = (i < NN) ? g_deg[i] : 0;
        }
#pragma unroll
        for (int j = 1; j < 8; j++) v[j] += v[j - 1];
        int x = v[7];
#pragma unroll
        for (int o = 1; o < 32; o <<= 1) {
            int y = __shfl_up_sync(0xffffffffu, x, o);
            if (lane >= o) x += y;
        }
        if (lane == 31) warp_sums[w] = x;
        __syncthreads();
        if (w == 0) {
            int s = warp_sums[lane];
#pragma unroll
            for (int o = 1; o < 32; o <<= 1) {
                int y = __shfl_up_sync(0xffffffffu, s, o);
                if (lane >= o) s += y;
            }
            warp_sums[lane] = s;
        }
        __syncthreads();
        int off = (x - v[7]) + (w > 0 ? warp_sums[w - 1] : 0) + s_carry;
#pragma unroll
        for (int j = 0; j < 8; j++) {
            int i = i0 + j;
            if (i < NN) {
                g_rowptr[i + 1] = off + v[j];
                g_cursor[i] = off + (j > 0 ? v[j - 1] : 0);
            }
        }
        __syncthreads();
        if (tid == 0) s_carry += warp_sums[31];
        __syncthreads();
    }
}

__global__ void scatter_kernel(const int* __restrict__ edge) {
    int e = blockIdx.x * blockDim.x + threadIdx.x;
    if (e < EE) {
        int r = edge[e];
        int c = edge[EE + e];
        int pos = atomicAdd(&g_cursor[r], 1);
        g_cols[pos] = c;
    }
}

// ============== SINGLE-PASS fused softmax + SpMM, unroll x4 (MLP=4) ==============
// Warp = (row, head-pair hp); lane owns 4 feats (8B fp16). Groups of 4 edges:
// all 8 loads issued before any compute -> 4 overlapped L2 round-trips.
__global__ __launch_bounds__(256) void aggregate_kernel(float* __restrict__ out) {
    int gw = (blockIdx.x * blockDim.x + threadIdx.x) >> 5;
    int lane = threadIdx.x & 31;
    int row = gw >> 1;
    int hp = gw & 1;
    if (row >= NN) return;
    int start = g_rowptr[row];
    int end = g_rowptr[row + 1];
    float* orow = out + (size_t)row * FEAT + hp * 128 + lane * 4;
    if (start == end) {
        *(float4*)orow = make_float4(0.f, 0.f, 0.f, 0.f);
        return;
    }
    float2 hl2 = *(const float2*)(g_hl + row * NHEAD + hp * 2);
    int head_local = lane >> 4;
    float hlv = head_local ? hl2.y : hl2.x;

    float den = 0.f;
    float4 acc = make_float4(0.f, 0.f, 0.f, 0.f);
    const size_t fofs = hp * 128 + lane * 4;

    int j = start;
    for (; j + 3 < end; j += 4) {
        int c0 = g_cols[j], c1 = g_cols[j + 1], c2 = g_cols[j + 2], c3 = g_cols[j + 3];
        float2 r0 = *(const float2*)(g_hr + c0 * NHEAD + hp * 2);
        float2 r1 = *(const float2*)(g_hr + c1 * NHEAD + hp * 2);
        float2 r2 = *(const float2*)(g_hr + c2 * NHEAD + hp * 2);
        float2 r3 = *(const float2*)(g_hr + c3 * NHEAD + hp * 2);
        float2 v0 = *(const float2*)(g_hh + (size_t)c0 * FEAT + fofs);
        float2 v1 = *(const float2*)(g_hh + (size_t)c1 * FEAT + fofs);
        float2 v2 = *(const float2*)(g_hh + (size_t)c2 * FEAT + fofs);
        float2 v3 = *(const float2*)(g_hh + (size_t)c3 * FEAT + fofs);
        float e0 = hlv + (head_local ? r0.y : r0.x); e0 = e0 > 0.f ? e0 : ALPHA * e0;
        float e1 = hlv + (head_local ? r1.y : r1.x); e1 = e1 > 0.f ? e1 : ALPHA * e1;
        float e2 = hlv + (head_local ? r2.y : r2.x); e2 = e2 > 0.f ? e2 : ALPHA * e2;
        float e3 = hlv + (head_local ? r3.y : r3.x); e3 = e3 > 0.f ? e3 : ALPHA * e3;
        float w0 = __expf(e0), w1 = __expf(e1), w2 = __expf(e2), w3 = __expf(e3);
        den += (w0 + w1) + (w2 + w3);
        float2 f;
        f = __half22float2(*(__half2*)&v0.x);
        acc.x = fmaf(w0, f.x, acc.x); acc.y = fmaf(w0, f.y, acc.y);
        f = __half22float2(*(__half2*)&v0.y);
        acc.z = fmaf(w0, f.x, acc.z); acc.w = fmaf(w0, f.y, acc.w);
        f = __half22float2(*(__half2*)&v1.x);
        acc.x = fmaf(w1, f.x, acc.x); acc.y = fmaf(w1, f.y, acc.y);
        f = __half22float2(*(__half2*)&v1.y);
        acc.z = fmaf(w1, f.x, acc.z); acc.w = fmaf(w1, f.y, acc.w);
        f = __half22float2(*(__half2*)&v2.x);
        acc.x = fmaf(w2, f.x, acc.x); acc.y = fmaf(w2, f.y, acc.y);
        f = __half22float2(*(__half2*)&v2.y);
        acc.z = fmaf(w2, f.x, acc.z); acc.w = fmaf(w2, f.y, acc.w);
        f = __half22float2(*(__half2*)&v3.x);
        acc.x = fmaf(w3, f.x, acc.x); acc.y = fmaf(w3, f.y, acc.y);
        f = __half22float2(*(__half2*)&v3.y);
        acc.z = fmaf(w3, f.x, acc.z); acc.w = fmaf(w3, f.y, acc.w);
    }
    for (; j < end; j++) {
        int c = g_cols[j];
        float2 r = *(const float2*)(g_hr + c * NHEAD + hp * 2);
        float2 v = *(const float2*)(g_hh + (size_t)c * FEAT + fofs);
        float e = hlv + (head_local ? r.y : r.x);
        e = e > 0.f ? e : ALPHA * e;
        float w = __expf(e);
        den += w;
        float2 f01 = __half22float2(*(__half2*)&v.x);
        float2 f23 = __half22float2(*(__half2*)&v.y);
        acc.x = fmaf(w, f01.x, acc.x); acc.y = fmaf(w, f01.y, acc.y);
        acc.z = fmaf(w, f23.x, acc.z); acc.w = fmaf(w, f23.y, acc.w);
    }
    float inv = 1.0f / den;
    *(float4*)orow = make_float4(acc.x * inv, acc.y * inv, acc.z * inv, acc.w * inv);
}

// ================= launch =================
extern "C" void kernel_launch(void* const* d_in, const int* in_sizes, int n_in,
                              void* d_out, int out_size) {
    const float* x  = (const float*)d_in[0];
    const int*   eg = (const int*)d_in[1];
    const float* W  = (const float*)d_in[2];
    const float* al = (const float*)d_in[3];
    const float* ar = (const float*)d_in[4];
    float* out = (float*)d_out;

    // ncu capture window lands on launch #4 -> gemm stays profiled.
    prep_wf_kernel<<<64, 256>>>(W);
    zero_deg_kernel<<<(NN + 255) / 256, 256>>>();
    hist_kernel<<<(EE + 255) / 256, 256>>>(eg);

    dim3 ggrid(NHEAD, (NN + 127) / 128);
    gemm_fp16_kernel<<<ggrid, 128>>>(x, al, ar);

    scan_kernel<<<1, 1024>>>();
    scatter_kernel<<<(EE + 255) / 256, 256>>>(eg);

    int agg_warps = NN * 2;
    aggregate_kernel<<<(agg_warps * 32 + 255) / 256, 256>>>(out);
}

// round 8
// speedup vs baseline: 1.6925x; 1.0223x over previous
#include <cuda_runtime.h>
#include <cuda_fp16.h>
#include <math_constants.h>
#include <cstdint>

#define NN   50000
#define EE   800000
#define INF_ 256
#define OUTF 64
#define NHEAD 4
#define FEAT (NHEAD*OUTF)   // 256
#define ALPHA 0.2f

// -------- device scratch (static; allocation-free; zero-initialized) --------
__device__ __half g_hh[(size_t)NN * FEAT];   // projected features, fp16
__device__ float g_hl[NN * NHEAD];
__device__ float g_hr[NN * NHEAD];
__device__ uint2 g_Wf[NHEAD * 16 * 8 * 32];  // W in fp16 mma-fragment order (128KB)
__device__ int   g_deg[NN];                  // zeroed by scan after use (and at init)
__device__ int   g_rowptr[NN + 1];
__device__ int   g_cursor[NN];
__device__ int   g_cols[EE];

#define HIST_BLOCKS 3125
#define GEMM_BLOCKS 1564   // 4 heads x 391 mtiles

// ============ launch 1: histogram + W fragment prep (blockIdx split) ============
// B frag (m16n8k16, col): thread(g=lane>>2, tg=lane&3): b0={W[k0+2tg][n], W[k0+2tg+1][n]},
// b1 = same at k+8, n = hb*64 + nblk*8 + g, k0 = ks*16.
__global__ __launch_bounds__(256) void hist_prep_kernel(const int* __restrict__ edge,
                                                        const float* __restrict__ W) {
    int b = blockIdx.x;
    if (b < HIST_BLOCKS) {
        int e = b * 256 + threadIdx.x;
        if (e < EE) atomicAdd(&g_deg[edge[e]], 1);
    } else {
        int idx = (b - HIST_BLOCKS) * 256 + threadIdx.x;
        if (idx >= NHEAD * 16 * 8 * 32) return;
        int lane = idx & 31;
        int nblk = (idx >> 5) & 7;
        int ks   = (idx >> 8) & 15;
        int hb   = idx >> 12;
        int g = lane >> 2, tg = lane & 3;
        int n = hb * OUTF + nblk * 8 + g;
        int k0 = ks * 16 + 2 * tg;
        __half2 b0 = __floats2half2_rn(W[(size_t)k0 * FEAT + n],
                                       W[(size_t)(k0 + 1) * FEAT + n]);
        __half2 b1 = __floats2half2_rn(W[(size_t)(k0 + 8) * FEAT + n],
                                       W[(size_t)(k0 + 9) * FEAT + n]);
        g_Wf[idx] = make_uint2(*(unsigned*)&b0, *(unsigned*)&b1);
    }
}

// ============ launch 2: single-block scan; also RESETS g_deg for next replay ============
__global__ __launch_bounds__(1024) void scan_kernel() {
    __shared__ int warp_sums[32];
    __shared__ int s_carry;
    int tid = threadIdx.x;
    int lane = tid & 31, w = tid >> 5;
    if (tid == 0) { s_carry = 0; g_rowptr[0] = 0; }
    __syncthreads();
    for (int base = 0; base < NN; base += 8192) {
        int i0 = base + tid * 8;
        int v[8];
#pragma unroll
        for (int j = 0; j < 8; j++) {
            int i = i0 + j;
            v[j] = (i < NN) ? g_deg[i] : 0;
            if (i < NN) g_deg[i] = 0;              // reset for next graph replay
        }
#pragma unroll
        for (int j = 1; j < 8; j++) v[j] += v[j - 1];
        int x = v[7];
#pragma unroll
        for (int o = 1; o < 32; o <<= 1) {
            int y = __shfl_up_sync(0xffffffffu, x, o);
            if (lane >= o) x += y;
        }
        if (lane == 31) warp_sums[w] = x;
        __syncthreads();
        if (w == 0) {
            int s = warp_sums[lane];
#pragma unroll
            for (int o = 1; o < 32; o <<= 1) {
                int y = __shfl_up_sync(0xffffffffu, s, o);
                if (lane >= o) s += y;
            }
            warp_sums[lane] = s;
        }
        __syncthreads();
        int off = (x - v[7]) + (w > 0 ? warp_sums[w - 1] : 0) + s_carry;
#pragma unroll
        for (int j = 0; j < 8; j++) {
            int i = i0 + j;
            if (i < NN) {
                g_rowptr[i + 1] = off + v[j];
                g_cursor[i] = off + (j > 0 ? v[j - 1] : 0);
            }
        }
        __syncthreads();
        if (tid == 0) s_carry += warp_sums[31];
        __syncthreads();
    }
}

// ============ launch 3: fp16 mma GEMM (+fused logits) | CSR scatter (split) ============
#define A_STAGE_B 8224   // bytes (2 kst * 4112)

__device__ __forceinline__ void mma_f16(float c[4], unsigned a0, unsigned a1,
                                        unsigned a2, unsigned a3,
                                        unsigned b0, unsigned b1) {
    asm volatile(
        "mma.sync.aligned.m16n8k16.row.col.f32.f16.f16.f32 "
        "{%0,%1,%2,%3}, {%4,%5,%6,%7}, {%8,%9}, {%0,%1,%2,%3};"
        : "+f"(c[0]), "+f"(c[1]), "+f"(c[2]), "+f"(c[3])
        : "r"(a0), "r"(a1), "r"(a2), "r"(a3), "r"(b0), "r"(b1));
}

__device__ __forceinline__ int a_sts_off(int r, int c4) {
    return ((c4 >> 4) ? 4112 : 0) + (r >> 4) * 512 +
           (((r & 7) * 4 + ((c4 & 7) >> 1)) << 4) + (((c4 >> 3) & 1) << 3) +
           (((r >> 3) & 1) << 2);
}

__global__ __launch_bounds__(128) void gemm_scatter_kernel(
    const float* __restrict__ X,
    const float* __restrict__ al, const float* __restrict__ ar,
    const int* __restrict__ edge) {
    __shared__ __align__(16) char sAbuf[2 * A_STAGE_B];

    if (blockIdx.x >= GEMM_BLOCKS) {
        // ---------------- scatter part ----------------
        int e = (blockIdx.x - GEMM_BLOCKS) * 128 + threadIdx.x;
        if (e < EE) {
            int r = edge[e];
            int c = edge[EE + e];
            int pos = atomicAdd(&g_cursor[r], 1);
            g_cols[pos] = c;
        }
        return;
    }

    // ---------------- GEMM part ----------------
    int tid = threadIdx.x;
    int lane = tid & 31;
    int wid = tid >> 5;
    int wm = wid >> 1, wn = wid & 1;
    int g = lane >> 2, tg = lane & 3;
    int hb = blockIdx.x & 3;                 // head
    int bm = (blockIdx.x >> 2) * 128;
    int bn = hb * OUTF;

    float acc[4][4][4];
#pragma unroll
    for (int mt = 0; mt < 4; mt++)
#pragma unroll
        for (int nt = 0; nt < 4; nt++)
#pragma unroll
            for (int q = 0; q < 4; q++) acc[mt][nt][q] = 0.f;

    const uint2* Wfb = g_Wf + hb * (16 * 8 * 32);

    float4 ra[8];
#pragma unroll
    for (int i = 0; i < 8; i++) {
        int f = tid + i * 128;
        int r = f >> 3, c4 = (f & 7) * 4;
        int row = bm + r;
        ra[i] = (row < NN) ? *(const float4*)(X + (size_t)row * INF_ + c4)
                           : make_float4(0.f, 0.f, 0.f, 0.f);
    }
#pragma unroll
    for (int i = 0; i < 8; i++) {
        int f = tid + i * 128;
        int r = f >> 3, c4 = (f & 7) * 4;
        char* p = sAbuf + a_sts_off(r, c4);
        *(__half2*)p = __floats2half2_rn(ra[i].x, ra[i].y);
        *(__half2*)(p + 16) = __floats2half2_rn(ra[i].z, ra[i].w);
    }
    uint2 bq[4], bqn[4];
#pragma unroll
    for (int nt = 0; nt < 4; nt++)
        bq[nt] = Wfb[(0 * 8 + wn * 4 + nt) * 32 + lane];
    __syncthreads();

    for (int kt = 0; kt < 8; kt++) {
        int st = kt & 1;
        const char* As = sAbuf + st * A_STAGE_B;
        if (kt < 7) {
            int k0 = (kt + 1) * 32;
#pragma unroll
            for (int i = 0; i < 8; i++) {
                int f = tid + i * 128;
                int r = f >> 3, c4 = (f & 7) * 4;
                int row = bm + r;
                ra[i] = (row < NN) ? *(const float4*)(X + (size_t)row * INF_ + k0 + c4)
                                   : make_float4(0.f, 0.f, 0.f, 0.f);
            }
        }
#pragma unroll
        for (int kst = 0; kst < 2; kst++) {
            int ks = kt * 2 + kst;
            if (ks < 15) {
#pragma unroll
                for (int nt = 0; nt < 4; nt++)
                    bqn[nt] = Wfb[((ks + 1) * 8 + wn * 4 + nt) * 32 + lane];
            }
            uint4 af[4];
#pragma unroll
            for (int mt = 0; mt < 4; mt++)
                af[mt] = *(const uint4*)(As + kst * 4112 + (wm * 4 + mt) * 512 +
                                         (g * 4 + tg) * 16);
#pragma unroll
            for (int mt = 0; mt < 4; mt++)
#pragma unroll
                for (int nt = 0; nt < 4; nt++)
                    mma_f16(acc[mt][nt], af[mt].x, af[mt].y, af[mt].z, af[mt].w,
                            bq[nt].x, bq[nt].y);
#pragma unroll
            for (int nt = 0; nt < 4; nt++) bq[nt] = bqn[nt];
        }
        if (kt < 7) {
            char* dA = sAbuf + (1 - st) * A_STAGE_B;
#pragma unroll
            for (int i = 0; i < 8; i++) {
                int f = tid + i * 128;
                int r = f >> 3, c4 = (f & 7) * 4;
                char* p = dA + a_sts_off(r, c4);
                *(__half2*)p = __floats2half2_rn(ra[i].x, ra[i].y);
                *(__half2*)(p + 16) = __floats2half2_rn(ra[i].z, ra[i].w);
            }
        }
        __syncthreads();
    }

    // epilogue: store h fp16; fused hl/hr logits
    const float* alh = al + hb * OUTF;
    const float* arh = ar + hb * OUTF;
    float plv[4][2] = {{0.f,0.f},{0.f,0.f},{0.f,0.f},{0.f,0.f}};
    float prv[4][2] = {{0.f,0.f},{0.f,0.f},{0.f,0.f},{0.f,0.f}};

#pragma unroll
    for (int mt = 0; mt < 4; mt++) {
#pragma unroll
        for (int nt = 0; nt < 4; nt++) {
            int row0 = bm + wm * 64 + mt * 16 + g;
            int cl = wn * 32 + nt * 8 + tg * 2;
            int col = bn + cl;
            if (row0 < NN)
                *(__half2*)(g_hh + (size_t)row0 * FEAT + col) =
                    __floats2half2_rn(acc[mt][nt][0], acc[mt][nt][1]);
            if (row0 + 8 < NN)
                *(__half2*)(g_hh + (size_t)(row0 + 8) * FEAT + col) =
                    __floats2half2_rn(acc[mt][nt][2], acc[mt][nt][3]);
            float a0l = alh[cl], a1l = alh[cl + 1];
            float a0r = arh[cl], a1r = arh[cl + 1];
            plv[mt][0] = fmaf(a0l, acc[mt][nt][0], fmaf(a1l, acc[mt][nt][1], plv[mt][0]));
            plv[mt][1] = fmaf(a0l, acc[mt][nt][2], fmaf(a1l, acc[mt][nt][3], plv[mt][1]));
            prv[mt][0] = fmaf(a0r, acc[mt][nt][0], fmaf(a1r, acc[mt][nt][1], prv[mt][0]));
            prv[mt][1] = fmaf(a0r, acc[mt][nt][2], fmaf(a1r, acc[mt][nt][3], prv[mt][1]));
        }
    }
#pragma unroll
    for (int off = 1; off < 4; off <<= 1) {
#pragma unroll
        for (int mt = 0; mt < 4; mt++)
#pragma unroll
            for (int rh = 0; rh < 2; rh++) {
                plv[mt][rh] += __shfl_xor_sync(0xffffffffu, plv[mt][rh], off);
                prv[mt][rh] += __shfl_xor_sync(0xffffffffu, prv[mt][rh], off);
            }
    }
    __syncthreads();
    float* sPL = (float*)sAbuf;          // [2][128]
    float* sPR = (float*)sAbuf + 256;
    if (tg == 0) {
#pragma unroll
        for (int mt = 0; mt < 4; mt++)
#pragma unroll
            for (int rh = 0; rh < 2; rh++) {
                int rowl = wm * 64 + mt * 16 + rh * 8 + g;
                sPL[wn * 128 + rowl] = plv[mt][rh];
                sPR[wn * 128 + rowl] = prv[mt][rh];
            }
    }
    __syncthreads();
    if (tid < 128) {
        int row = bm + tid;
        if (row < NN) {
            g_hl[row * NHEAD + hb] = sPL[tid] + sPL[128 + tid];
            g_hr[row * NHEAD + hb] = sPR[tid] + sPR[128 + tid];
        }
    }
}

// ============ launch 4: single-pass softmax+SpMM, ONE warp per row, all heads ============
// Lane owns 8 feats (16B): head = lane>>3. hl/hr are per-lane broadcast loads; all
// lanes of a head compute the identical weight -> per-head denominator needs no
// shuffle. Unroll x4 -> up to 8 independent loads in flight per warp.
__global__ __launch_bounds__(256) void aggregate_kernel(float* __restrict__ out) {
    int row = (blockIdx.x * blockDim.x + threadIdx.x) >> 5;
    int lane = threadIdx.x & 31;
    if (row >= NN) return;
    int start = g_rowptr[row];
    int end = g_rowptr[row + 1];
    float* orow = out + (size_t)row * FEAT + lane * 8;
    if (start == end) {
        float4 z = make_float4(0.f, 0.f, 0.f, 0.f);
        *(float4*)orow = z;
        *(float4*)(orow + 4) = z;
        return;
    }
    int hd = lane >> 3;
    float hlv = g_hl[row * NHEAD + hd];

    float den = 0.f;
    float acc[8] = {0.f, 0.f, 0.f, 0.f, 0.f, 0.f, 0.f, 0.f};
    const size_t fofs = lane * 8;

    int j = start;
    for (; j + 3 < end; j += 4) {
        int c0 = g_cols[j], c1 = g_cols[j + 1], c2 = g_cols[j + 2], c3 = g_cols[j + 3];
        float r0 = g_hr[c0 * NHEAD + hd];
        float r1 = g_hr[c1 * NHEAD + hd];
        float r2 = g_hr[c2 * NHEAD + hd];
        float r3 = g_hr[c3 * NHEAD + hd];
        uint4 v0 = *(const uint4*)(g_hh + (size_t)c0 * FEAT + fofs);
        uint4 v1 = *(const uint4*)(g_hh + (size_t)c1 * FEAT + fofs);
        uint4 v2 = *(const uint4*)(g_hh + (size_t)c2 * FEAT + fofs);
        uint4 v3 = *(const uint4*)(g_hh + (size_t)c3 * FEAT + fofs);
        float e0 = hlv + r0; e0 = e0 > 0.f ? e0 : ALPHA * e0;
        float e1 = hlv + r1; e1 = e1 > 0.f ? e1 : ALPHA * e1;
        float e2 = hlv + r2; e2 = e2 > 0.f ? e2 : ALPHA * e2;
        float e3 = hlv + r3; e3 = e3 > 0.f ? e3 : ALPHA * e3;
        float w0 = __expf(e0), w1 = __expf(e1), w2 = __expf(e2), w3 = __expf(e3);
        den += (w0 + w1) + (w2 + w3);
#pragma unroll
        for (int q = 0; q < 4; q++) {
            unsigned u0 = (&v0.x)[q], u1 = (&v1.x)[q], u2 = (&v2.x)[q], u3 = (&v3.x)[q];
            float2 f0 = __half22float2(*(__half2*)&u0);
            float2 f1 = __half22float2(*(__half2*)&u1);
            float2 f2 = __half22float2(*(__half2*)&u2);
            float2 f3 = __half22float2(*(__half2*)&u3);
            acc[q * 2 + 0] = fmaf(w0, f0.x, fmaf(w1, f1.x, fmaf(w2, f2.x,
                             fmaf(w3, f3.x, acc[q * 2 + 0]))));
            acc[q * 2 + 1] = fmaf(w0, f0.y, fmaf(w1, f1.y, fmaf(w2, f2.y,
                             fmaf(w3, f3.y, acc[q * 2 + 1]))));
        }
    }
    for (; j < end; j++) {
        int c = g_cols[j];
        float r = g_hr[c * NHEAD + hd];
        uint4 v = *(const uint4*)(g_hh + (size_t)c * FEAT + fofs);
        float e = hlv + r;
        e = e > 0.f ? e : ALPHA * e;
        float w = __expf(e);
        den += w;
#pragma unroll
        for (int q = 0; q < 4; q++) {
            unsigned u = (&v.x)[q];
            float2 f = __half22float2(*(__half2*)&u);
            acc[q * 2 + 0] = fmaf(w, f.x, acc[q * 2 + 0]);
            acc[q * 2 + 1] = fmaf(w, f.y, acc[q * 2 + 1]);
        }
    }
    float inv = 1.0f / den;
    *(float4*)orow = make_float4(acc[0] * inv, acc[1] * inv, acc[2] * inv, acc[3] * inv);
    *(float4*)(orow + 4) = make_float4(acc[4] * inv, acc[5] * inv, acc[6] * inv, acc[7] * inv);
}

// ================= launch =================
extern "C" void kernel_launch(void* const* d_in, const int* in_sizes, int n_in,
                              void* d_out, int out_size) {
    const float* x  = (const float*)d_in[0];
    const int*   eg = (const int*)d_in[1];
    const float* W  = (const float*)d_in[2];
    const float* al = (const float*)d_in[3];
    const float* ar = (const float*)d_in[4];
    float* out = (float*)d_out;

    // Exactly 4 launches; capture window (#4) lands on aggregate_kernel.
    hist_prep_kernel<<<HIST_BLOCKS + 64, 256>>>(eg, W);
    scan_kernel<<<1, 1024>>>();
    gemm_scatter_kernel<<<GEMM_BLOCKS + (EE + 127) / 128, 128>>>(x, al, ar, eg);
    aggregate_kernel<<<(NN * 32 + 255) / 256, 256>>>(out);
}